// round 8
// baseline (speedup 1.0000x reference)
#include <cuda_runtime.h>
#include <math.h>

#define NT_ 4096
#define NA_ 4096
#define NS_ 1024
#define NALL_ 9216
#define FEAT_ 128
#define COM_ 64
#define MPD_ 64
#define EMB_ 64
#define NCLS_ 3

constexpr size_t MAT = (size_t)NT_ * NT_;

// ---------------- arena layout (floats) ----------------
constexpr size_t OFF_M0   = 0;              // G_targ
constexpr size_t OFF_M1   = OFF_M0 + MAT;   // SEM_pap
constexpr size_t OFF_M2   = OFF_M1 + MAT;   // SEM_psp
constexpr size_t OFF_M3   = OFF_M2 + MAT;   // SIM_a -> F_a
constexpr size_t OFF_M4   = OFF_M3 + MAT;   // F_s
constexpr size_t OFF_M5   = OFF_M4 + MAT;   // S_a
constexpr size_t OFF_M6   = OFF_M5 + MAT;   // S_s
constexpr size_t OFF_M7   = OFF_M6 + MAT;   // new_adj (pre-symmetrize)
constexpr size_t OFF_SIMS = OFF_M7 + MAT;                    // sim_r_s 1024x1024
constexpr size_t OFF_ZT   = OFF_SIMS + (size_t)NS_ * NS_;    // 4096x256
constexpr size_t OFF_ZPAP = OFF_ZT   + (size_t)NT_ * 256;    // 4096x128
constexpr size_t OFF_ZPSP = OFF_ZPAP + (size_t)NT_ * 128;
constexpr size_t OFF_ZA   = OFF_ZPSP + (size_t)NT_ * 128;    // 4096x256
constexpr size_t OFF_ZS   = OFF_ZA   + (size_t)NT_ * 256;    // 1024x256
constexpr size_t OFF_ZFA  = OFF_ZS   + (size_t)NS_ * 256;    // 4096x256
constexpr size_t OFF_ZFS  = OFF_ZFA  + (size_t)NT_ * 256;
constexpr size_t OFF_ZSA  = OFF_ZFS  + (size_t)NT_ * 256;    // 4096x128
constexpr size_t OFF_ZSS  = OFF_ZSA  + (size_t)NT_ * 128;
constexpr size_t OFF_FPA  = OFF_ZSS  + (size_t)NT_ * 128;    // feat_prop_a 4096x128
constexpr size_t OFF_FPS  = OFF_FPA  + (size_t)NT_ * FEAT_;
constexpr size_t OFF_SWA  = OFF_FPS  + (size_t)NT_ * FEAT_;  // simW_a 4096x64
constexpr size_t OFF_SWS  = OFF_SWA  + (size_t)NT_ * COM_;   // simW_s 1024x64
constexpr size_t OFF_THA  = OFF_SWS  + (size_t)NS_ * COM_;   // topo_hid_a
constexpr size_t OFF_THS  = OFF_THA  + (size_t)NT_ * COM_;
constexpr size_t OFF_H0   = OFF_THS  + (size_t)NT_ * COM_;   // 4096x64
constexpr size_t OFF_X1   = OFF_H0   + (size_t)NT_ * EMB_;   // 4096x64
constexpr size_t OFF_H2   = OFF_X1   + (size_t)NT_ * EMB_;   // 4096x3
constexpr size_t OFF_X2   = OFF_H2   + (size_t)NT_ * NCLS_;  // 4096x3
constexpr size_t OFF_PART = OFF_X2   + (size_t)NT_ * NCLS_;  // split-K partials 8x4096x64
constexpr size_t OFF_CPART= OFF_PART + (size_t)8 * NT_ * 64; // colsum partials 7 slots x 32 x 4096
constexpr size_t CSLOT    = (size_t)32 * NT_;
constexpr size_t OFF_RPART= OFF_CPART + (size_t)7 * CSLOT;   // ca7 rowsum partials 32 x 4096
constexpr size_t OFF_COEF = OFF_RPART + CSLOT;               // c0..c6, cs_na (8 x NT_)
constexpr size_t OFF_RS   = OFF_COEF + (size_t)8 * NT_;      // rs_na
constexpr size_t OFF_SW   = OFF_RS + NT_;                    // softmaxed channel weights (8)
constexpr size_t ARENA_SZ = OFF_SW + 8;

__device__ float g_arena[ARENA_SZ];

constexpr int MAXNNZ_A = 512;
constexpr int MAXNNZ_S = 256;
constexpr size_t IOFF_IDXA = 0;
constexpr size_t IOFF_IDXS = IOFF_IDXA + (size_t)NT_ * MAXNNZ_A;
constexpr size_t IOFF_CNTA = IOFF_IDXS + (size_t)NT_ * MAXNNZ_S;
constexpr size_t IOFF_CNTS = IOFF_CNTA + NT_;
constexpr size_t IARENA_SZ = IOFF_CNTS + NT_;
__device__ int g_iarena[IARENA_SZ];

// ---------------- batched symmetric thresholded syrk ----------------
// Each job: C = thresh(A A^T) on an n x n output (n multiple of 128), with
// optional fused column-L1 partials. Upper-triangle blocks compute; mirrors
// write the transposed tile. blockIdx.z selects the job; blocks outside a
// job's n/128 grid exit immediately (lets small jobs ride along with big ones).
struct SymJob {
    const float* A;
    float* C;
    float* cpart;   // nullptr -> no colsum partials
    int n;
    int K;
    float th;
};
struct SymJobs { SymJob j[5]; };

__global__ __launch_bounds__(256)
void gemm_sym_batch_k(SymJobs jobs)
{
    __shared__ float As[2][8][128];
    __shared__ float Bs[2][8][128];
    __shared__ float Red2[128 * 17];

    const SymJob job = jobs.j[blockIdx.z];
    const int nb = job.n >> 7;
    if ((int)blockIdx.x >= nb || (int)blockIdx.y >= nb) return;
    if (blockIdx.x < blockIdx.y) return;   // symmetric: upper triangle only

    const int tid = threadIdx.x;
    const int tx = tid & 15, ty = tid >> 4;
    const int row0 = blockIdx.y * 128, col0 = blockIdx.x * 128;
    const int N = job.n, K = job.K;
    const float th = job.th;
    const float* __restrict__ A = job.A;
    float* __restrict__ C = job.C;

    float acc[8][8];
#pragma unroll
    for (int i = 0; i < 8; i++)
#pragma unroll
        for (int j = 0; j < 8; j++) acc[i][j] = 0.f;

    const int lr = tid >> 1;           // 0..127
    const int lc = (tid & 1) << 2;     // 0,4

    float4 av, bv;
    auto ldg_tile = [&](int k0) {
        av = *reinterpret_cast<const float4*>(A + (size_t)(row0 + lr) * K + k0 + lc);
        bv = *reinterpret_cast<const float4*>(A + (size_t)(col0 + lr) * K + k0 + lc);
    };
    auto sts_tile = [&](int b) {
        As[b][lc + 0][lr] = av.x; As[b][lc + 1][lr] = av.y;
        As[b][lc + 2][lr] = av.z; As[b][lc + 3][lr] = av.w;
        Bs[b][lc + 0][lr] = bv.x; Bs[b][lc + 1][lr] = bv.y;
        Bs[b][lc + 2][lr] = bv.z; Bs[b][lc + 3][lr] = bv.w;
    };

    ldg_tile(0);
    sts_tile(0);
    __syncthreads();

    int buf = 0;
    for (int k0 = 0; k0 < K; k0 += 8) {
        const bool more = (k0 + 8) < K;
        if (more) ldg_tile(k0 + 8);
#pragma unroll
        for (int kk = 0; kk < 8; kk++) {
            float af[8], bf[8];
            *reinterpret_cast<float4*>(af)     = *reinterpret_cast<const float4*>(&As[buf][kk][ty * 8]);
            *reinterpret_cast<float4*>(af + 4) = *reinterpret_cast<const float4*>(&As[buf][kk][ty * 8 + 4]);
            *reinterpret_cast<float4*>(bf)     = *reinterpret_cast<const float4*>(&Bs[buf][kk][tx * 8]);
            *reinterpret_cast<float4*>(bf + 4) = *reinterpret_cast<const float4*>(&Bs[buf][kk][tx * 8 + 4]);
#pragma unroll
            for (int i = 0; i < 8; i++)
#pragma unroll
                for (int j = 0; j < 8; j++)
                    acc[i][j] += af[i] * bf[j];
        }
        if (more) sts_tile(buf ^ 1);
        __syncthreads();
        buf ^= 1;
    }

    // threshold in-register, write original tile, accumulate colsum partials
    float csum[8];
#pragma unroll
    for (int j = 0; j < 8; j++) csum[j] = 0.f;

#pragma unroll
    for (int i = 0; i < 8; i++) {
        int r = row0 + ty * 8 + i;
#pragma unroll
        for (int j = 0; j < 8; j++) {
            float v = acc[i][j];
            if (v < th) v = 0.f;
            acc[i][j] = v;
            csum[j] += v;   // entries nonneg after threshold (th > 0)
            C[(size_t)r * N + col0 + tx * 8 + j] = v;
        }
    }

    const bool do_csum = (job.cpart != nullptr);
    if (do_csum) {
        // reuse As as a [16][128] reduction buffer (mainloop done, As dead)
        float* red = &As[0][0][0];
#pragma unroll
        for (int j = 0; j < 8; j++) red[ty * 128 + tx * 8 + j] = csum[j];
        __syncthreads();
        if (tid < 128) {
            float s = 0.f;
#pragma unroll
            for (int t = 0; t < 16; t++) s += red[t * 128 + tid];
            job.cpart[(size_t)blockIdx.y * N + col0 + tid] = s;
        }
    }

    if (blockIdx.x > blockIdx.y) {
        // mirror write: C[c][r]; per-thread 8 consecutive r -> 32B sectors
#pragma unroll
        for (int j = 0; j < 8; j++) {
            int c = col0 + tx * 8 + j;
            float t0[4] = {acc[0][j], acc[1][j], acc[2][j], acc[3][j]};
            float t1[4] = {acc[4][j], acc[5][j], acc[6][j], acc[7][j]};
            size_t base = (size_t)c * N + row0 + ty * 8;
            *reinterpret_cast<float4*>(&C[base])     = *reinterpret_cast<float4*>(t0);
            *reinterpret_cast<float4*>(&C[base + 4]) = *reinterpret_cast<float4*>(t1);
        }
        if (do_csum) {
            // mirror colsum: column (row0+ty*8+i), partial = sum_j acc[i][j]
            __syncthreads();
#pragma unroll
            for (int i = 0; i < 8; i++) {
                float s = 0.f;
#pragma unroll
                for (int j = 0; j < 8; j++) s += acc[i][j];
                Red2[(ty * 8 + i) * 17 + tx] = s;
            }
            __syncthreads();
            if (tid < 128) {
                float s = 0.f;
#pragma unroll
                for (int t = 0; t < 16; t++) s += Red2[tid * 17 + t];
                job.cpart[(size_t)blockIdx.x * N + row0 + tid] = s;
            }
        }
    }
}

// ---------------- plain NN GEMM (128x128 tile, split-K via gridDim.z) ----------------
__global__ __launch_bounds__(256)
void gemm_nn_k(const float* __restrict__ A, const float* __restrict__ B,
               float* __restrict__ C, int M, int N, int K)
{
    __shared__ float As[2][8][128];
    __shared__ float Bs[2][8][128];
    const int tid = threadIdx.x;
    const int tx = tid & 15, ty = tid >> 4;
    const int row0 = blockIdx.y * 128, col0 = blockIdx.x * 128;

    const int klen = K / gridDim.z;
    const int kbeg = blockIdx.z * klen;
    const int kend = kbeg + klen;
    C += (size_t)blockIdx.z * (size_t)M * N;

    float acc[8][8];
#pragma unroll
    for (int i = 0; i < 8; i++)
#pragma unroll
        for (int j = 0; j < 8; j++) acc[i][j] = 0.f;

    const int lr  = tid >> 1;
    const int lc  = (tid & 1) << 2;
    const int bnr = tid >> 5;
    const int bnc = (tid & 31) << 2;

    float4 av, bv;
    auto ldg_tile = [&](int k0) {
        av = make_float4(0.f, 0.f, 0.f, 0.f);
        {
            int r = row0 + lr;
            if (r < M) av = *reinterpret_cast<const float4*>(A + (size_t)r * K + k0 + lc);
        }
        bv = make_float4(0.f, 0.f, 0.f, 0.f);
        {
            int c = col0 + bnc;
            if (c + 3 < N) bv = *reinterpret_cast<const float4*>(B + (size_t)(k0 + bnr) * N + c);
        }
    };
    auto sts_tile = [&](int b) {
        As[b][lc + 0][lr] = av.x; As[b][lc + 1][lr] = av.y;
        As[b][lc + 2][lr] = av.z; As[b][lc + 3][lr] = av.w;
        *reinterpret_cast<float4*>(&Bs[b][bnr][bnc]) = bv;
    };

    ldg_tile(kbeg);
    sts_tile(0);
    __syncthreads();

    int buf = 0;
    for (int k0 = kbeg; k0 < kend; k0 += 8) {
        const bool more = (k0 + 8) < kend;
        if (more) ldg_tile(k0 + 8);
#pragma unroll
        for (int kk = 0; kk < 8; kk++) {
            float af[8], bf[8];
            *reinterpret_cast<float4*>(af)     = *reinterpret_cast<const float4*>(&As[buf][kk][ty * 8]);
            *reinterpret_cast<float4*>(af + 4) = *reinterpret_cast<const float4*>(&As[buf][kk][ty * 8 + 4]);
            *reinterpret_cast<float4*>(bf)     = *reinterpret_cast<const float4*>(&Bs[buf][kk][tx * 8]);
            *reinterpret_cast<float4*>(bf + 4) = *reinterpret_cast<const float4*>(&Bs[buf][kk][tx * 8 + 4]);
#pragma unroll
            for (int i = 0; i < 8; i++)
#pragma unroll
                for (int j = 0; j < 8; j++)
                    acc[i][j] += af[i] * bf[j];
        }
        if (more) sts_tile(buf ^ 1);
        __syncthreads();
        buf ^= 1;
    }
#pragma unroll
    for (int i = 0; i < 8; i++) {
        int r = row0 + ty * 8 + i;
        if (r >= M) continue;
#pragma unroll
        for (int j = 0; j < 8; j++) {
            int c = col0 + tx * 8 + j;
            if (c >= N) continue;
            C[(size_t)r * N + c] = acc[i][j];
        }
    }
}

// reduce split-K partials: out[e] = sum_z part[z*mn+e] (+bias[e%N]) (relu?)
__global__ void reduce_split_k(const float* __restrict__ part, int splits, size_t mn,
                               int N, const float* __restrict__ bias, int relu,
                               float* __restrict__ out)
{
    for (size_t e = (size_t)blockIdx.x * blockDim.x + threadIdx.x; e < mn;
         e += (size_t)gridDim.x * blockDim.x) {
        float s = 0.f;
        for (int z = 0; z < splits; z++) s += part[(size_t)z * mn + e];
        if (bias) s += bias[(int)(e % N)];
        if (relu) s = fmaxf(s, 0.f);
        out[e] = s;
    }
}

// ---------------- Z prep: Z[:, h*d:(h+1)*d] = L2(X∘w_h) / sqrt(H) ----------------
__global__ void prep_z_k(const float* __restrict__ X, int d,
                         const float* __restrict__ w, int H,
                         float* __restrict__ Z, float invsqH)
{
    __shared__ float red[128];
    int row = blockIdx.x;
    int t = threadIdx.x;
    for (int h = 0; h < H; h++) {
        float v = 0.f;
        if (t < d) v = X[(size_t)row * d + t] * w[h * d + t];
        red[t] = v * v;
        __syncthreads();
        for (int s = 64; s > 0; s >>= 1) {
            if (t < s) red[t] += red[t + s];
            __syncthreads();
        }
        float nrm = sqrtf(red[0]);
        if (t < d) Z[(size_t)row * (H * d) + h * d + t] = v / fmaxf(nrm, 1e-12f) * invsqH;
        __syncthreads();
    }
}

// ---------------- CSR build (deterministic ballot-compaction, warp/row) ----------------
__global__ void build_csr_k(const float* __restrict__ adj, int ld, int coloff, int ncols,
                            int* __restrict__ idx, int* __restrict__ cnt, int maxnnz)
{
    int wrp = (blockIdx.x * blockDim.x + threadIdx.x) >> 5;
    int lane = threadIdx.x & 31;
    if (wrp >= NT_) return;
    const float* rowp = adj + (size_t)wrp * ld + coloff;
    int base = 0;
    for (int j0 = 0; j0 < ncols; j0 += 32) {
        float v = rowp[j0 + lane];
        unsigned m = __ballot_sync(0xffffffffu, v != 0.f);
        if (v != 0.f) {
            int r = __popc(m & ((1u << lane) - 1u));
            int p = base + r;
            if (p < maxnnz) idx[(size_t)wrp * maxnnz + p] = j0 + lane;
        }
        base += __popc(m);
    }
    if (lane == 0) cnt[wrp] = base < maxnnz ? base : maxnnz;
}

// ---------------- SpMM: out[i,:] = sum_{k in nnz(i)} B[k,:] (+bias) ----------------
__global__ void spmm_k(const int* __restrict__ idx, const int* __restrict__ cnt, int maxnnz,
                       const float* __restrict__ B, int ncols,
                       const float* __restrict__ bias, float* __restrict__ out)
{
    int row = blockIdx.x;
    int j = threadIdx.x;
    int c = cnt[row];
    const int* ip = idx + (size_t)row * maxnnz;
    float acc = bias ? bias[j] : 0.f;
    for (int t = 0; t < c; t++) {
        int r = __ldg(&ip[t]);
        acc += B[(size_t)r * ncols + j];
    }
    out[(size_t)row * ncols + j] = acc;
}

// ---------------- collapsed channel-attention coefficients ----------------
// Reads the 7 CPART slices directly (fixed order -> deterministic), finalizes
// the 7 base column sums inline, then collapses the two-level attention tree.
// All channel matrices are nonnegative, so each L1-normalized column sums to
// exactly 1 (or 0 if the column is empty):
//   new_adj[i][j] = sum_k c_k[j] * M_k[i][j],  cs_na[j] = sum_k c_k[j]*cs_k[j].
__global__ void coef_k(const float* __restrict__ cpart, const float* __restrict__ sw,
                       float* __restrict__ coef)
{
    int j = blockIdx.x * blockDim.x + threadIdx.x;
    if (j >= NT_) return;
    float cs[7];
#pragma unroll
    for (int k = 0; k < 7; k++) {
        const float* p = cpart + (size_t)k * CSLOT + j;
        float s = 0.f;
#pragma unroll
        for (int z = 0; z < 32; z++) s += p[(size_t)z * NT_];
        cs[k] = s;
    }
    float g0 = sw[0], g1 = sw[1], f0 = sw[2], f1 = sw[3];
    float v0 = sw[4], v1 = sw[5], v2 = sw[6], v3 = sw[7];
    const float eps = 1e-12f;
    float csem = g0 * (cs[1] > 0.f ? 1.f : 0.f) + g1 * (cs[2] > 0.f ? 1.f : 0.f);
    float cfp  = f0 * (cs[3] > 0.f ? 1.f : 0.f) + f1 * (cs[4] > 0.f ? 1.f : 0.f);
    float ctt  = f0 * (cs[5] > 0.f ? 1.f : 0.f) + f1 * (cs[6] > 0.f ? 1.f : 0.f);
    float ksem = v1 / fmaxf(csem, eps);
    float kfp  = v2 / fmaxf(cfp, eps);
    float ktt  = v3 / fmaxf(ctt, eps);
    float c[7];
    c[0] = v0 / fmaxf(cs[0], eps);
    c[1] = ksem * g0 / fmaxf(cs[1], eps);
    c[2] = ksem * g1 / fmaxf(cs[2], eps);
    c[3] = kfp * f0 / fmaxf(cs[3], eps);
    c[4] = kfp * f1 / fmaxf(cs[4], eps);
    c[5] = ktt * f0 / fmaxf(cs[5], eps);
    c[6] = ktt * f1 / fmaxf(cs[6], eps);
    float cna = 0.f;
#pragma unroll
    for (int k = 0; k < 7; k++) {
        coef[(size_t)k * NT_ + j] = c[k];
        cna += c[k] * cs[k];
    }
    coef[(size_t)7 * NT_ + j] = cna;   // cs_na
}

// ---------------- fused 7-channel combine + row-sum partials ----------------
// out = sum_k c_k[j] * M_k ; also emits per-(col-tile, row) row-sum partials
// (entries are nonnegative, so |.| = identity). grid (32, 32), block 128;
// thread owns one column, streams 128 rows in 8-row chunks with a two-stage
// shared reduction (single writer per (col-tile,row) -> deterministic).
__global__ void ca7rs_k(const float* __restrict__ M0, const float* __restrict__ M1,
                        const float* __restrict__ M2, const float* __restrict__ M3,
                        const float* __restrict__ M4, const float* __restrict__ M5,
                        const float* __restrict__ M6,
                        const float* __restrict__ coef, float* __restrict__ out,
                        float* __restrict__ rpart)
{
    __shared__ float sh[8][129];
    __shared__ float sh2[8][16];
    int tid = threadIdx.x;
    int j = blockIdx.x * 128 + tid;
    int r0 = blockIdx.y * 128;
    float c0 = coef[0 * NT_ + j], c1 = coef[1 * NT_ + j], c2 = coef[2 * NT_ + j];
    float c3 = coef[3 * NT_ + j], c4 = coef[4 * NT_ + j];
    float c5 = coef[5 * NT_ + j], c6 = coef[6 * NT_ + j];
    int g = tid & 15, rr2 = tid >> 4;   // reduction role: lane-group, row
    for (int ch = 0; ch < 16; ch++) {
        int rbase = r0 + ch * 8;
#pragma unroll
        for (int rr = 0; rr < 8; rr++) {
            size_t e = (size_t)(rbase + rr) * NT_ + j;
            float v = c0 * M0[e] + c1 * M1[e] + c2 * M2[e] + c3 * M3[e]
                    + c4 * M4[e] + c5 * M5[e] + c6 * M6[e];
            out[e] = v;
            sh[rr][tid] = v;
        }
        __syncthreads();
        {
            float s = 0.f;
#pragma unroll
            for (int t = 0; t < 8; t++) s += sh[rr2][g * 8 + t];
            sh2[rr2][g] = s;
        }
        __syncthreads();
        if (tid < 8) {
            float s = 0.f;
#pragma unroll
            for (int t = 0; t < 16; t++) s += sh2[tid][t];
            rpart[(size_t)blockIdx.x * NT_ + rbase + tid] = s;
        }
        __syncthreads();
    }
}

// finalize row sums: rs[r] = sum over 32 col-tile slices
__global__ void rowfin_k(const float* __restrict__ rpart, float* __restrict__ rs)
{
    int r = blockIdx.x * blockDim.x + threadIdx.x;
    if (r >= NT_) return;
    float s = 0.f;
#pragma unroll
    for (int z = 0; z < 32; z++) s += rpart[(size_t)z * NT_ + r];
    rs[r] = s;
}

// ---------------- symmetrize + column-L1 normalize ----------------
__global__ void sym_norm_k(const float* __restrict__ A, const float* __restrict__ cs,
                           const float* __restrict__ rs, float* __restrict__ out, int n)
{
    __shared__ float t[32][33];
    int bi = blockIdx.y * 32, bj = blockIdx.x * 32;
    for (int r = threadIdx.y; r < 32; r += 8)
        t[r][threadIdx.x] = A[(size_t)(bj + r) * n + bi + threadIdx.x];
    __syncthreads();
    for (int r = threadIdx.y; r < 32; r += 8) {
        int i = bi + r, j = bj + threadIdx.x;
        float v = A[(size_t)i * n + j] + t[threadIdx.x][r];
        out[(size_t)i * n + j] = v / fmaxf(cs[j] + rs[j], 1e-12f);
    }
}

// ---------------- small-N (N=3) GEMM, warp/row ----------------
__global__ void gemm_n3_k(const float* __restrict__ A, const float* __restrict__ B,
                          const float* __restrict__ bias, float* __restrict__ C,
                          int M, int K)
{
    int wrp = (blockIdx.x * blockDim.x + threadIdx.x) >> 5;
    int lane = threadIdx.x & 31;
    if (wrp >= M) return;
    const float* row = A + (size_t)wrp * K;
    float a0 = 0.f, a1 = 0.f, a2 = 0.f;
    for (int k = lane; k < K; k += 32) {
        float a = row[k];
        a0 += a * __ldg(&B[k * 3 + 0]);
        a1 += a * __ldg(&B[k * 3 + 1]);
        a2 += a * __ldg(&B[k * 3 + 2]);
    }
    for (int o = 16; o > 0; o >>= 1) {
        a0 += __shfl_down_sync(0xffffffffu, a0, o);
        a1 += __shfl_down_sync(0xffffffffu, a1, o);
        a2 += __shfl_down_sync(0xffffffffu, a2, o);
    }
    if (lane == 0) {
        if (bias) { a0 += bias[0]; a1 += bias[1]; a2 += bias[2]; }
        C[(size_t)wrp * 3 + 0] = a0;
        C[(size_t)wrp * 3 + 1] = a1;
        C[(size_t)wrp * 3 + 2] = a2;
    }
}

__global__ void logsoftmax_k(const float* __restrict__ X, float* __restrict__ out, int M)
{
    int i = blockIdx.x * blockDim.x + threadIdx.x;
    if (i >= M) return;
    float x0 = X[i * 3], x1 = X[i * 3 + 1], x2 = X[i * 3 + 2];
    float m = fmaxf(x0, fmaxf(x1, x2));
    float s = expf(x0 - m) + expf(x1 - m) + expf(x2 - m);
    float l = m + logf(s);
    out[i * 3] = x0 - l; out[i * 3 + 1] = x1 - l; out[i * 3 + 2] = x2 - l;
}

__global__ void prep_sw_k(const float* __restrict__ w2a, const float* __restrict__ w2b,
                          const float* __restrict__ w4, float* __restrict__ sw)
{
    if (threadIdx.x == 0 && blockIdx.x == 0) {
        {
            float m = fmaxf(w2a[0], w2a[1]);
            float e0 = expf(w2a[0] - m), e1 = expf(w2a[1] - m), s = e0 + e1;
            sw[0] = e0 / s; sw[1] = e1 / s;
        }
        {
            float m = fmaxf(w2b[0], w2b[1]);
            float e0 = expf(w2b[0] - m), e1 = expf(w2b[1] - m), s = e0 + e1;
            sw[2] = e0 / s; sw[3] = e1 / s;
        }
        {
            float m = fmaxf(fmaxf(w4[0], w4[1]), fmaxf(w4[2], w4[3]));
            float e[4]; float s = 0.f;
            for (int i = 0; i < 4; i++) { e[i] = expf(w4[i] - m); s += e[i]; }
            for (int i = 0; i < 4; i++) sw[4 + i] = e[i] / s;
        }
    }
}

// ---------------- launch ----------------
extern "C" void kernel_launch(void* const* d_in, const int* in_sizes, int n_in,
                              void* d_out, int out_size)
{
    const float* features  = (const float*)d_in[0];
    const float* adj_ori   = (const float*)d_in[1];
    const float* mp_pap    = (const float*)d_in[2];
    const float* mp_psp    = (const float*)d_in[3];
    const float* fgo_w     = (const float*)d_in[6];
    const float* fpo_w     = (const float*)d_in[7];
    const float* sgg_pap_w = (const float*)d_in[8];
    const float* sgg_psp_w = (const float*)d_in[9];
    const float* sg_agg_w  = (const float*)d_in[10];
    const float* f_agg_f_w = (const float*)d_in[11];
    const float* f_agg_w   = (const float*)d_in[12];
    const float* topo_W_a  = (const float*)d_in[13];
    const float* topo_b_a  = (const float*)d_in[14];
    const float* topo_W_s  = (const float*)d_in[15];
    const float* topo_b_s  = (const float*)d_in[16];
    const float* fgt_w_a   = (const float*)d_in[17];
    const float* fgt_w_s   = (const float*)d_in[18];
    const float* gcn_W1    = (const float*)d_in[19];
    const float* gcn_b1    = (const float*)d_in[20];
    const float* gcn_W2    = (const float*)d_in[21];
    const float* gcn_b2    = (const float*)d_in[22];

    float* arena = nullptr;
    int* iarena = nullptr;
    cudaGetSymbolAddress((void**)&arena, g_arena);
    cudaGetSymbolAddress((void**)&iarena, g_iarena);

    float* M0 = arena + OFF_M0;
    float* M1 = arena + OFF_M1;
    float* M2 = arena + OFF_M2;
    float* M3 = arena + OFF_M3;
    float* M4 = arena + OFF_M4;
    float* M5 = arena + OFF_M5;
    float* M6 = arena + OFF_M6;
    float* M7 = arena + OFF_M7;
    float* SIMS = arena + OFF_SIMS;
    float* ZT  = arena + OFF_ZT;
    float* ZPAP = arena + OFF_ZPAP;
    float* ZPSP = arena + OFF_ZPSP;
    float* ZA  = arena + OFF_ZA;
    float* ZS  = arena + OFF_ZS;
    float* ZFA = arena + OFF_ZFA;
    float* ZFS = arena + OFF_ZFS;
    float* ZSA = arena + OFF_ZSA;
    float* ZSS = arena + OFF_ZSS;
    float* FPA = arena + OFF_FPA;
    float* FPS = arena + OFF_FPS;
    float* SWA = arena + OFF_SWA;
    float* SWS = arena + OFF_SWS;
    float* THA = arena + OFF_THA;
    float* THS = arena + OFF_THS;
    float* H0B = arena + OFF_H0;
    float* X1B = arena + OFF_X1;
    float* H2B = arena + OFF_H2;
    float* X2B = arena + OFF_X2;
    float* PART = arena + OFF_PART;
    float* CPART = arena + OFF_CPART;
    float* RPART = arena + OFF_RPART;
    float* COEF = arena + OFF_COEF;
    float* RS   = arena + OFF_RS;
    float* SW = arena + OFF_SW;

    int* IDXA = iarena + IOFF_IDXA;
    int* IDXS = iarena + IOFF_IDXS;
    int* CNTA = iarena + IOFF_CNTA;
    int* CNTS = iarena + IOFF_CNTS;

    float* logits = (float*)d_out;
    float* out_adj = (float*)d_out + (size_t)NT_ * NCLS_;

    const float ISQH = 0.70710678118654752f; // 1/sqrt(2)

    // scalars
    prep_sw_k<<<1, 32>>>(sg_agg_w, f_agg_f_w, f_agg_w, SW);

    // Z preps (round 1)
    prep_z_k<<<NT_, 128>>>(features, FEAT_, fgo_w, 2, ZT, ISQH);
    prep_z_k<<<NT_, 128>>>(mp_pap, MPD_, sgg_pap_w, 2, ZPAP, ISQH);
    prep_z_k<<<NT_, 128>>>(mp_psp, MPD_, sgg_psp_w, 2, ZPSP, ISQH);
    prep_z_k<<<NT_, 128>>>(features + (size_t)NT_ * FEAT_, FEAT_, fgo_w, 2, ZA, ISQH);
    prep_z_k<<<NS_, 128>>>(features + (size_t)(NT_ + NA_) * FEAT_, FEAT_, fgo_w, 2, ZS, ISQH);

    // CSR build (deterministic, sorted)
    build_csr_k<<<(NT_ * 32 + 255) / 256, 256>>>(adj_ori, NALL_, NT_, NA_, IDXA, CNTA, MAXNNZ_A);
    build_csr_k<<<(NT_ * 32 + 255) / 256, 256>>>(adj_ori, NALL_, NT_ + NA_, NS_, IDXS, CNTS, MAXNNZ_S);

    // feat_prop = ori_g @ fmat_r (SpMM; adj entries are exactly 1.0)
    spmm_k<<<NT_, 128>>>(IDXA, CNTA, MAXNNZ_A, features + (size_t)NT_ * FEAT_, FEAT_, nullptr, FPA);
    spmm_k<<<NT_, 128>>>(IDXS, CNTS, MAXNNZ_S, features + (size_t)(NT_ + NA_) * FEAT_, FEAT_, nullptr, FPS);

    float* CP0 = CPART + 0 * CSLOT;
    float* CP1 = CPART + 1 * CSLOT;
    float* CP2 = CPART + 2 * CSLOT;
    float* CP3 = CPART + 3 * CSLOT;
    float* CP4 = CPART + 4 * CSLOT;
    float* CP5 = CPART + 5 * CSLOT;
    float* CP6 = CPART + 6 * CSLOT;

    // round-1 sym GEMM batch: all five thresholded Z Z^T graphs in ONE launch
    {
        SymJobs jb{};
        jb.j[0] = {ZT,   M0,   CP0,     NT_, 256, 0.1f};
        jb.j[1] = {ZPAP, M1,   CP1,     NT_, 128, 0.1f};
        jb.j[2] = {ZPSP, M2,   CP2,     NT_, 128, 0.1f};
        jb.j[3] = {ZA,   M3,   nullptr, NT_, 256, 0.1f};
        jb.j[4] = {ZS,   SIMS, nullptr, NS_, 256, 0.1f};
        gemm_sym_batch_k<<<dim3(32, 32, 5), 256>>>(jb);
    }

    // simW = sim_r @ topo_W  (split-K=8 for occupancy), then topo_hid = ori_g @ simW + b
    gemm_nn_k<<<dim3(1, 32, 8), 256>>>(M3, topo_W_a, PART, NT_, COM_, NT_);
    reduce_split_k<<<512, 256>>>(PART, 8, (size_t)NT_ * COM_, COM_, nullptr, 0, SWA);
    gemm_nn_k<<<dim3(1, 8, 8), 256>>>(SIMS, topo_W_s, PART, NS_, COM_, NS_);
    reduce_split_k<<<128, 256>>>(PART, 8, (size_t)NS_ * COM_, COM_, nullptr, 0, SWS);
    spmm_k<<<NT_, 64>>>(IDXA, CNTA, MAXNNZ_A, SWA, COM_, topo_b_a, THA);
    spmm_k<<<NT_, 64>>>(IDXS, CNTS, MAXNNZ_S, SWS, COM_, topo_b_s, THS);

    // Z preps (round 2)
    prep_z_k<<<NT_, 128>>>(FPA, FEAT_, fpo_w, 2, ZFA, ISQH);
    prep_z_k<<<NT_, 128>>>(FPS, FEAT_, fpo_w, 2, ZFS, ISQH);
    prep_z_k<<<NT_, 128>>>(THA, COM_, fgt_w_a, 2, ZSA, ISQH);
    prep_z_k<<<NT_, 128>>>(THS, COM_, fgt_w_s, 2, ZSS, ISQH);

    // round-2 sym GEMM batch (M3 safe to overwrite: NN gemm above is ordered first)
    {
        SymJobs jb{};
        jb.j[0] = {ZFA, M3, CP3, NT_, 256, 0.2f};
        jb.j[1] = {ZFS, M4, CP4, NT_, 256, 0.2f};
        jb.j[2] = {ZSA, M5, CP5, NT_, 128, 0.1f};
        jb.j[3] = {ZSS, M6, CP6, NT_, 128, 0.1f};
        gemm_sym_batch_k<<<dim3(32, 32, 4), 256>>>(jb);
    }

    // collapsed channel attention: finalize colsums + coefficients, then ONE
    // fused 7-input combine that also emits row-sum partials
    coef_k<<<16, 256>>>(CPART, SW, COEF);
    ca7rs_k<<<dim3(32, 32, 1), 128>>>(M0, M1, M2, M3, M4, M5, M6, COEF, M7, RPART);
    rowfin_k<<<16, 256>>>(RPART, RS);

    // symmetrize + L1 column-normalize -> output adjacency
    sym_norm_k<<<dim3(128, 128, 1), dim3(32, 8, 1)>>>(M7, COEF + 7 * NT_, RS, out_adj, NT_);

    // GCN
    gemm_nn_k<<<dim3(1, 32, 1), 256>>>(features, gcn_W1, H0B, NT_, EMB_, FEAT_);
    gemm_nn_k<<<dim3(1, 32, 8), 256>>>(out_adj, H0B, PART, NT_, EMB_, NT_);
    reduce_split_k<<<512, 256>>>(PART, 8, (size_t)NT_ * EMB_, EMB_, gcn_b1, 1, X1B);
    gemm_n3_k<<<(NT_ * 32 + 255) / 256, 256>>>(X1B, gcn_W2, nullptr, H2B, NT_, EMB_);
    gemm_n3_k<<<(NT_ * 32 + 255) / 256, 256>>>(out_adj, H2B, gcn_b2, X2B, NT_, NT_);
    logsoftmax_k<<<(NT_ + 255) / 256, 256>>>(X2B, logits, NT_);
}

// round 10
// speedup vs baseline: 1.0270x; 1.0270x over previous
#include <cuda_runtime.h>
#include <math.h>

#define NT_ 4096
#define NA_ 4096
#define NS_ 1024
#define NALL_ 9216
#define FEAT_ 128
#define COM_ 64
#define MPD_ 64
#define EMB_ 64
#define NCLS_ 3

constexpr size_t MAT = (size_t)NT_ * NT_;

// ---------------- arena layout (floats) ----------------
constexpr size_t OFF_M0   = 0;              // G_targ
constexpr size_t OFF_M1   = OFF_M0 + MAT;   // SEM_pap
constexpr size_t OFF_M2   = OFF_M1 + MAT;   // SEM_psp
constexpr size_t OFF_M3   = OFF_M2 + MAT;   // SIM_a -> F_a
constexpr size_t OFF_M4   = OFF_M3 + MAT;   // F_s
constexpr size_t OFF_M5   = OFF_M4 + MAT;   // S_a
constexpr size_t OFF_M6   = OFF_M5 + MAT;   // S_s
constexpr size_t OFF_M7   = OFF_M6 + MAT;   // new_adj (pre-symmetrize)
constexpr size_t OFF_SIMS = OFF_M7 + MAT;                    // sim_r_s 1024x1024
constexpr size_t OFF_ZT   = OFF_SIMS + (size_t)NS_ * NS_;    // 4096x256
constexpr size_t OFF_ZPAP = OFF_ZT   + (size_t)NT_ * 256;    // 4096x128
constexpr size_t OFF_ZPSP = OFF_ZPAP + (size_t)NT_ * 128;
constexpr size_t OFF_ZA   = OFF_ZPSP + (size_t)NT_ * 128;    // 4096x256
constexpr size_t OFF_ZS   = OFF_ZA   + (size_t)NT_ * 256;    // 1024x256
constexpr size_t OFF_ZFA  = OFF_ZS   + (size_t)NS_ * 256;    // 4096x256
constexpr size_t OFF_ZFS  = OFF_ZFA  + (size_t)NT_ * 256;
constexpr size_t OFF_ZSA  = OFF_ZFS  + (size_t)NT_ * 256;    // 4096x128
constexpr size_t OFF_ZSS  = OFF_ZSA  + (size_t)NT_ * 128;
constexpr size_t OFF_FPA  = OFF_ZSS  + (size_t)NT_ * 128;    // feat_prop_a 4096x128
constexpr size_t OFF_FPS  = OFF_FPA  + (size_t)NT_ * FEAT_;
constexpr size_t OFF_SWA  = OFF_FPS  + (size_t)NT_ * FEAT_;  // simW_a 4096x64
constexpr size_t OFF_SWS  = OFF_SWA  + (size_t)NT_ * COM_;   // simW_s 1024x64
constexpr size_t OFF_THA  = OFF_SWS  + (size_t)NS_ * COM_;   // topo_hid_a
constexpr size_t OFF_THS  = OFF_THA  + (size_t)NT_ * COM_;
constexpr size_t OFF_H0   = OFF_THS  + (size_t)NT_ * COM_;   // 4096x64
constexpr size_t OFF_X1   = OFF_H0   + (size_t)NT_ * EMB_;   // 4096x64
constexpr size_t OFF_H2   = OFF_X1   + (size_t)NT_ * EMB_;   // 4096x3
constexpr size_t OFF_X2   = OFF_H2   + (size_t)NT_ * NCLS_;  // 4096x3
constexpr size_t OFF_PART = OFF_X2   + (size_t)NT_ * NCLS_;  // split-K partials 8x4096x64
constexpr size_t OFF_CPART= OFF_PART + (size_t)8 * NT_ * 64; // colsum partials 7 slots x 32 x 4096
constexpr size_t CSLOT    = (size_t)32 * NT_;
constexpr size_t OFF_RPART= OFF_CPART + (size_t)7 * CSLOT;   // ca7 rowsum partials 32 x 4096
constexpr size_t OFF_COEF = OFF_RPART + CSLOT;               // c0..c6, cs_na (8 x NT_)
constexpr size_t OFF_DEN  = OFF_COEF + (size_t)8 * NT_;      // fmax(cs_na+rs_na, eps)
constexpr size_t OFF_SW   = OFF_DEN + NT_;                   // softmaxed channel weights (8)
constexpr size_t ARENA_SZ = OFF_SW + 8;

__device__ float g_arena[ARENA_SZ];

constexpr int MAXNNZ_A = 512;
constexpr int MAXNNZ_S = 256;
constexpr size_t IOFF_IDXA = 0;
constexpr size_t IOFF_IDXS = IOFF_IDXA + (size_t)NT_ * MAXNNZ_A;
constexpr size_t IOFF_CNTA = IOFF_IDXS + (size_t)NT_ * MAXNNZ_S;
constexpr size_t IOFF_CNTS = IOFF_CNTA + NT_;
constexpr size_t IARENA_SZ = IOFF_CNTS + NT_;
__device__ int g_iarena[IARENA_SZ];

// ---------------- batched symmetric thresholded syrk ----------------
// Each job: C = thresh(A A^T) on an n x n output (n multiple of 128), with
// optional fused column-L1 partials. Upper-triangle blocks compute; mirrors
// write the transposed tile. blockIdx.z selects the job; blocks outside a
// job's n/128 grid exit immediately (lets small jobs ride along with big ones).
struct SymJob {
    const float* A;
    float* C;
    float* cpart;   // nullptr -> no colsum partials
    int n;
    int K;
    float th;
};
struct SymJobs { SymJob j[5]; };

__global__ __launch_bounds__(256)
void gemm_sym_batch_k(SymJobs jobs)
{
    __shared__ float As[2][8][128];
    __shared__ float Bs[2][8][128];
    __shared__ float Red2[128 * 17];

    const SymJob job = jobs.j[blockIdx.z];
    const int nb = job.n >> 7;
    if ((int)blockIdx.x >= nb || (int)blockIdx.y >= nb) return;
    if (blockIdx.x < blockIdx.y) return;   // symmetric: upper triangle only

    const int tid = threadIdx.x;
    const int tx = tid & 15, ty = tid >> 4;
    const int row0 = blockIdx.y * 128, col0 = blockIdx.x * 128;
    const int N = job.n, K = job.K;
    const float th = job.th;
    const float* __restrict__ A = job.A;
    float* __restrict__ C = job.C;

    float acc[8][8];
#pragma unroll
    for (int i = 0; i < 8; i++)
#pragma unroll
        for (int j = 0; j < 8; j++) acc[i][j] = 0.f;

    const int lr = tid >> 1;           // 0..127
    const int lc = (tid & 1) << 2;     // 0,4

    float4 av, bv;
    auto ldg_tile = [&](int k0) {
        av = *reinterpret_cast<const float4*>(A + (size_t)(row0 + lr) * K + k0 + lc);
        bv = *reinterpret_cast<const float4*>(A + (size_t)(col0 + lr) * K + k0 + lc);
    };
    auto sts_tile = [&](int b) {
        As[b][lc + 0][lr] = av.x; As[b][lc + 1][lr] = av.y;
        As[b][lc + 2][lr] = av.z; As[b][lc + 3][lr] = av.w;
        Bs[b][lc + 0][lr] = bv.x; Bs[b][lc + 1][lr] = bv.y;
        Bs[b][lc + 2][lr] = bv.z; Bs[b][lc + 3][lr] = bv.w;
    };

    ldg_tile(0);
    sts_tile(0);
    __syncthreads();

    int buf = 0;
    for (int k0 = 0; k0 < K; k0 += 8) {
        const bool more = (k0 + 8) < K;
        if (more) ldg_tile(k0 + 8);
#pragma unroll
        for (int kk = 0; kk < 8; kk++) {
            float af[8], bf[8];
            *reinterpret_cast<float4*>(af)     = *reinterpret_cast<const float4*>(&As[buf][kk][ty * 8]);
            *reinterpret_cast<float4*>(af + 4) = *reinterpret_cast<const float4*>(&As[buf][kk][ty * 8 + 4]);
            *reinterpret_cast<float4*>(bf)     = *reinterpret_cast<const float4*>(&Bs[buf][kk][tx * 8]);
            *reinterpret_cast<float4*>(bf + 4) = *reinterpret_cast<const float4*>(&Bs[buf][kk][tx * 8 + 4]);
#pragma unroll
            for (int i = 0; i < 8; i++)
#pragma unroll
                for (int j = 0; j < 8; j++)
                    acc[i][j] += af[i] * bf[j];
        }
        if (more) sts_tile(buf ^ 1);
        __syncthreads();
        buf ^= 1;
    }

    // threshold in-register, write original tile, accumulate colsum partials
    float csum[8];
#pragma unroll
    for (int j = 0; j < 8; j++) csum[j] = 0.f;

#pragma unroll
    for (int i = 0; i < 8; i++) {
        int r = row0 + ty * 8 + i;
#pragma unroll
        for (int j = 0; j < 8; j++) {
            float v = acc[i][j];
            if (v < th) v = 0.f;
            acc[i][j] = v;
            csum[j] += v;   // entries nonneg after threshold (th > 0)
            C[(size_t)r * N + col0 + tx * 8 + j] = v;
        }
    }

    const bool do_csum = (job.cpart != nullptr);
    if (do_csum) {
        // reuse As as a [16][128] reduction buffer (mainloop done, As dead)
        float* red = &As[0][0][0];
#pragma unroll
        for (int j = 0; j < 8; j++) red[ty * 128 + tx * 8 + j] = csum[j];
        __syncthreads();
        if (tid < 128) {
            float s = 0.f;
#pragma unroll
            for (int t = 0; t < 16; t++) s += red[t * 128 + tid];
            job.cpart[(size_t)blockIdx.y * N + col0 + tid] = s;
        }
    }

    if (blockIdx.x > blockIdx.y) {
        // mirror write: C[c][r]; per-thread 8 consecutive r -> 32B sectors
#pragma unroll
        for (int j = 0; j < 8; j++) {
            int c = col0 + tx * 8 + j;
            float t0[4] = {acc[0][j], acc[1][j], acc[2][j], acc[3][j]};
            float t1[4] = {acc[4][j], acc[5][j], acc[6][j], acc[7][j]};
            size_t base = (size_t)c * N + row0 + ty * 8;
            *reinterpret_cast<float4*>(&C[base])     = *reinterpret_cast<float4*>(t0);
            *reinterpret_cast<float4*>(&C[base + 4]) = *reinterpret_cast<float4*>(t1);
        }
        if (do_csum) {
            // mirror colsum: column (row0+ty*8+i), partial = sum_j acc[i][j]
            __syncthreads();
#pragma unroll
            for (int i = 0; i < 8; i++) {
                float s = 0.f;
#pragma unroll
                for (int j = 0; j < 8; j++) s += acc[i][j];
                Red2[(ty * 8 + i) * 17 + tx] = s;
            }
            __syncthreads();
            if (tid < 128) {
                float s = 0.f;
#pragma unroll
                for (int t = 0; t < 16; t++) s += Red2[tid * 17 + t];
                job.cpart[(size_t)blockIdx.x * N + row0 + tid] = s;
            }
        }
    }
}

// ---------------- plain NN GEMM (128x128 tile, split-K via gridDim.z) ----------------
__global__ __launch_bounds__(256)
void gemm_nn_k(const float* __restrict__ A, const float* __restrict__ B,
               float* __restrict__ C, int M, int N, int K)
{
    __shared__ float As[2][8][128];
    __shared__ float Bs[2][8][128];
    const int tid = threadIdx.x;
    const int tx = tid & 15, ty = tid >> 4;
    const int row0 = blockIdx.y * 128, col0 = blockIdx.x * 128;

    const int klen = K / gridDim.z;
    const int kbeg = blockIdx.z * klen;
    const int kend = kbeg + klen;
    C += (size_t)blockIdx.z * (size_t)M * N;

    float acc[8][8];
#pragma unroll
    for (int i = 0; i < 8; i++)
#pragma unroll
        for (int j = 0; j < 8; j++) acc[i][j] = 0.f;

    const int lr  = tid >> 1;
    const int lc  = (tid & 1) << 2;
    const int bnr = tid >> 5;
    const int bnc = (tid & 31) << 2;

    float4 av, bv;
    auto ldg_tile = [&](int k0) {
        av = make_float4(0.f, 0.f, 0.f, 0.f);
        {
            int r = row0 + lr;
            if (r < M) av = *reinterpret_cast<const float4*>(A + (size_t)r * K + k0 + lc);
        }
        bv = make_float4(0.f, 0.f, 0.f, 0.f);
        {
            int c = col0 + bnc;
            if (c + 3 < N) bv = *reinterpret_cast<const float4*>(B + (size_t)(k0 + bnr) * N + c);
        }
    };
    auto sts_tile = [&](int b) {
        As[b][lc + 0][lr] = av.x; As[b][lc + 1][lr] = av.y;
        As[b][lc + 2][lr] = av.z; As[b][lc + 3][lr] = av.w;
        *reinterpret_cast<float4*>(&Bs[b][bnr][bnc]) = bv;
    };

    ldg_tile(kbeg);
    sts_tile(0);
    __syncthreads();

    int buf = 0;
    for (int k0 = kbeg; k0 < kend; k0 += 8) {
        const bool more = (k0 + 8) < kend;
        if (more) ldg_tile(k0 + 8);
#pragma unroll
        for (int kk = 0; kk < 8; kk++) {
            float af[8], bf[8];
            *reinterpret_cast<float4*>(af)     = *reinterpret_cast<const float4*>(&As[buf][kk][ty * 8]);
            *reinterpret_cast<float4*>(af + 4) = *reinterpret_cast<const float4*>(&As[buf][kk][ty * 8 + 4]);
            *reinterpret_cast<float4*>(bf)     = *reinterpret_cast<const float4*>(&Bs[buf][kk][tx * 8]);
            *reinterpret_cast<float4*>(bf + 4) = *reinterpret_cast<const float4*>(&Bs[buf][kk][tx * 8 + 4]);
#pragma unroll
            for (int i = 0; i < 8; i++)
#pragma unroll
                for (int j = 0; j < 8; j++)
                    acc[i][j] += af[i] * bf[j];
        }
        if (more) sts_tile(buf ^ 1);
        __syncthreads();
        buf ^= 1;
    }
#pragma unroll
    for (int i = 0; i < 8; i++) {
        int r = row0 + ty * 8 + i;
        if (r >= M) continue;
#pragma unroll
        for (int j = 0; j < 8; j++) {
            int c = col0 + tx * 8 + j;
            if (c >= N) continue;
            C[(size_t)r * N + c] = acc[i][j];
        }
    }
}

// reduce split-K partials: out[e] = sum_z part[z*mn+e] (+bias[e%N]) (relu?)
__global__ void reduce_split_k(const float* __restrict__ part, int splits, size_t mn,
                               int N, const float* __restrict__ bias, int relu,
                               float* __restrict__ out)
{
    for (size_t e = (size_t)blockIdx.x * blockDim.x + threadIdx.x; e < mn;
         e += (size_t)gridDim.x * blockDim.x) {
        float s = 0.f;
        for (int z = 0; z < splits; z++) s += part[(size_t)z * mn + e];
        if (bias) s += bias[(int)(e % N)];
        if (relu) s = fmaxf(s, 0.f);
        out[e] = s;
    }
}

// ---------------- Z prep (warp-per-row, both heads fused, shuffle reduce) ----------------
// Z[:, h*d:(h+1)*d] = L2(X∘w_h) / sqrt(H), H=2, d in {64,128}
__global__ void prep_z_k(const float* __restrict__ X, int d, int nrows,
                         const float* __restrict__ w,
                         float* __restrict__ Z, float invsqH)
{
    int wrp = (blockIdx.x * blockDim.x + threadIdx.x) >> 5;
    int lane = threadIdx.x & 31;
    if (wrp >= nrows) return;
    const float* xr = X + (size_t)wrp * d;
    int nper = d >> 5;   // 2 or 4
    float v0[4], v1[4];
    float s0 = 0.f, s1 = 0.f;
#pragma unroll 4
    for (int i = 0; i < nper; i++) {
        int c = lane + 32 * i;
        float x = xr[c];
        float a = x * __ldg(&w[c]);
        float b = x * __ldg(&w[d + c]);
        v0[i] = a; v1[i] = b;
        s0 += a * a; s1 += b * b;
    }
#pragma unroll
    for (int o = 16; o > 0; o >>= 1) {
        s0 += __shfl_xor_sync(0xffffffffu, s0, o);
        s1 += __shfl_xor_sync(0xffffffffu, s1, o);
    }
    float n0 = invsqH / fmaxf(sqrtf(s0), 1e-12f);
    float n1 = invsqH / fmaxf(sqrtf(s1), 1e-12f);
    float* zr = Z + (size_t)wrp * 2 * d;
#pragma unroll 4
    for (int i = 0; i < nper; i++) {
        int c = lane + 32 * i;
        zr[c] = v0[i] * n0;
        zr[d + c] = v1[i] * n1;
    }
}

// ---------------- CSR build (deterministic ballot-compaction, warp/row) ----------------
__global__ void build_csr_k(const float* __restrict__ adj, int ld, int coloff, int ncols,
                            int* __restrict__ idx, int* __restrict__ cnt, int maxnnz)
{
    int wrp = (blockIdx.x * blockDim.x + threadIdx.x) >> 5;
    int lane = threadIdx.x & 31;
    if (wrp >= NT_) return;
    const float* rowp = adj + (size_t)wrp * ld + coloff;
    int base = 0;
    for (int j0 = 0; j0 < ncols; j0 += 32) {
        float v = rowp[j0 + lane];
        unsigned m = __ballot_sync(0xffffffffu, v != 0.f);
        if (v != 0.f) {
            int r = __popc(m & ((1u << lane) - 1u));
            int p = base + r;
            if (p < maxnnz) idx[(size_t)wrp * maxnnz + p] = j0 + lane;
        }
        base += __popc(m);
    }
    if (lane == 0) cnt[wrp] = base < maxnnz ? base : maxnnz;
}

// ---------------- SpMM: out[i,:] = sum_{k in nnz(i)} B[k,:] (+bias) ----------------
__global__ void spmm_k(const int* __restrict__ idx, const int* __restrict__ cnt, int maxnnz,
                       const float* __restrict__ B, int ncols,
                       const float* __restrict__ bias, float* __restrict__ out)
{
    int row = blockIdx.x;
    int j = threadIdx.x;
    int c = cnt[row];
    const int* ip = idx + (size_t)row * maxnnz;
    float acc = bias ? bias[j] : 0.f;
    for (int t = 0; t < c; t++) {
        int r = __ldg(&ip[t]);
        acc += B[(size_t)r * ncols + j];
    }
    out[(size_t)row * ncols + j] = acc;
}

// ---------------- collapsed channel-attention coefficients ----------------
// Reads the 7 CPART slices directly (fixed order -> deterministic), finalizes
// the 7 base column sums inline, then collapses the two-level attention tree.
// All channel matrices are nonnegative, so each L1-normalized column sums to
// exactly 1 (or 0 if the column is empty):
//   new_adj[i][j] = sum_k c_k[j] * M_k[i][j],  cs_na[j] = sum_k c_k[j]*cs_k[j].
__global__ void coef_k(const float* __restrict__ cpart, const float* __restrict__ sw,
                       float* __restrict__ coef)
{
    int j = blockIdx.x * blockDim.x + threadIdx.x;
    if (j >= NT_) return;
    float cs[7];
#pragma unroll
    for (int k = 0; k < 7; k++) {
        const float* p = cpart + (size_t)k * CSLOT + j;
        float s = 0.f;
#pragma unroll
        for (int z = 0; z < 32; z++) s += p[(size_t)z * NT_];
        cs[k] = s;
    }
    float g0 = sw[0], g1 = sw[1], f0 = sw[2], f1 = sw[3];
    float v0 = sw[4], v1 = sw[5], v2 = sw[6], v3 = sw[7];
    const float eps = 1e-12f;
    float csem = g0 * (cs[1] > 0.f ? 1.f : 0.f) + g1 * (cs[2] > 0.f ? 1.f : 0.f);
    float cfp  = f0 * (cs[3] > 0.f ? 1.f : 0.f) + f1 * (cs[4] > 0.f ? 1.f : 0.f);
    float ctt  = f0 * (cs[5] > 0.f ? 1.f : 0.f) + f1 * (cs[6] > 0.f ? 1.f : 0.f);
    float ksem = v1 / fmaxf(csem, eps);
    float kfp  = v2 / fmaxf(cfp, eps);
    float ktt  = v3 / fmaxf(ctt, eps);
    float c[7];
    c[0] = v0 / fmaxf(cs[0], eps);
    c[1] = ksem * g0 / fmaxf(cs[1], eps);
    c[2] = ksem * g1 / fmaxf(cs[2], eps);
    c[3] = kfp * f0 / fmaxf(cs[3], eps);
    c[4] = kfp * f1 / fmaxf(cs[4], eps);
    c[5] = ktt * f0 / fmaxf(cs[5], eps);
    c[6] = ktt * f1 / fmaxf(cs[6], eps);
    float cna = 0.f;
#pragma unroll
    for (int k = 0; k < 7; k++) {
        coef[(size_t)k * NT_ + j] = c[k];
        cna += c[k] * cs[k];
    }
    coef[(size_t)7 * NT_ + j] = cna;   // cs_na
}

// ---------------- fused 7-channel combine + row-sum partials ----------------
// out = sum_k c_k[j] * M_k ; also emits per-(col-tile, row) row-sum partials
// (entries are nonnegative, so |.| = identity). grid (32, 32), block 128;
// thread owns one column, streams 128 rows in 8-row chunks with a two-stage
// shared reduction (single writer per (col-tile,row) -> deterministic).
__global__ void ca7rs_k(const float* __restrict__ M0, const float* __restrict__ M1,
                        const float* __restrict__ M2, const float* __restrict__ M3,
                        const float* __restrict__ M4, const float* __restrict__ M5,
                        const float* __restrict__ M6,
                        const float* __restrict__ coef, float* __restrict__ out,
                        float* __restrict__ rpart)
{
    __shared__ float sh[8][129];
    __shared__ float sh2[8][16];
    int tid = threadIdx.x;
    int j = blockIdx.x * 128 + tid;
    int r0 = blockIdx.y * 128;
    float c0 = coef[0 * NT_ + j], c1 = coef[1 * NT_ + j], c2 = coef[2 * NT_ + j];
    float c3 = coef[3 * NT_ + j], c4 = coef[4 * NT_ + j];
    float c5 = coef[5 * NT_ + j], c6 = coef[6 * NT_ + j];
    int g = tid & 15, rr2 = tid >> 4;   // reduction role: lane-group, row
    for (int ch = 0; ch < 16; ch++) {
        int rbase = r0 + ch * 8;
#pragma unroll
        for (int rr = 0; rr < 8; rr++) {
            size_t e = (size_t)(rbase + rr) * NT_ + j;
            float v = c0 * M0[e] + c1 * M1[e] + c2 * M2[e] + c3 * M3[e]
                    + c4 * M4[e] + c5 * M5[e] + c6 * M6[e];
            out[e] = v;
            sh[rr][tid] = v;
        }
        __syncthreads();
        {
            float s = 0.f;
#pragma unroll
            for (int t = 0; t < 8; t++) s += sh[rr2][g * 8 + t];
            sh2[rr2][g] = s;
        }
        __syncthreads();
        if (tid < 8) {
            float s = 0.f;
#pragma unroll
            for (int t = 0; t < 16; t++) s += sh2[tid][t];
            rpart[(size_t)blockIdx.x * NT_ + rbase + tid] = s;
        }
        __syncthreads();
    }
}

// finalize denominator: den[r] = fmax(cs_na[r] + sum_z rpart[z][r], eps)
__global__ void denfin_k(const float* __restrict__ rpart, const float* __restrict__ cna,
                         float* __restrict__ den)
{
    int r = blockIdx.x * blockDim.x + threadIdx.x;
    if (r >= NT_) return;
    float s = 0.f;
#pragma unroll
    for (int z = 0; z < 32; z++) s += rpart[(size_t)z * NT_ + r];
    den[r] = fmaxf(cna[r] + s, 1e-12f);
}

// ---------------- symmetrize + column-L1 normalize (triangle blocks) ----------------
// Upper-triangle 32x32 block pair (I,J): read tile A[I,J] and mirror A[J,I]
// once each, write both normalized outputs. Every A element read exactly once.
__global__ void sym_norm_tri_k(const float* __restrict__ A, const float* __restrict__ den,
                               float* __restrict__ out, int n)
{
    if ((int)blockIdx.x < (int)blockIdx.y) return;
    __shared__ float T1[32][33];
    __shared__ float T2[32][33];
    int I = blockIdx.y * 32, J = blockIdx.x * 32;
    for (int r = threadIdx.y; r < 32; r += 8) {
        T1[r][threadIdx.x] = A[(size_t)(I + r) * n + J + threadIdx.x];
        T2[r][threadIdx.x] = A[(size_t)(J + r) * n + I + threadIdx.x];
    }
    __syncthreads();
    for (int r = threadIdx.y; r < 32; r += 8) {
        int j = J + threadIdx.x;
        out[(size_t)(I + r) * n + j] = (T1[r][threadIdx.x] + T2[threadIdx.x][r]) / den[j];
    }
    if (blockIdx.x > blockIdx.y) {
        for (int r = threadIdx.y; r < 32; r += 8) {
            int j = I + threadIdx.x;
            out[(size_t)(J + r) * n + j] = (T2[r][threadIdx.x] + T1[threadIdx.x][r]) / den[j];
        }
    }
}

// ---------------- small-N (N=3) GEMM, warp/row ----------------
__global__ void gemm_n3_k(const float* __restrict__ A, const float* __restrict__ B,
                          const float* __restrict__ bias, float* __restrict__ C,
                          int M, int K)
{
    int wrp = (blockIdx.x * blockDim.x + threadIdx.x) >> 5;
    int lane = threadIdx.x & 31;
    if (wrp >= M) return;
    const float* row = A + (size_t)wrp * K;
    float a0 = 0.f, a1 = 0.f, a2 = 0.f;
    for (int k = lane; k < K; k += 32) {
        float a = row[k];
        a0 += a * __ldg(&B[k * 3 + 0]);
        a1 += a * __ldg(&B[k * 3 + 1]);
        a2 += a * __ldg(&B[k * 3 + 2]);
    }
    for (int o = 16; o > 0; o >>= 1) {
        a0 += __shfl_down_sync(0xffffffffu, a0, o);
        a1 += __shfl_down_sync(0xffffffffu, a1, o);
        a2 += __shfl_down_sync(0xffffffffu, a2, o);
    }
    if (lane == 0) {
        if (bias) { a0 += bias[0]; a1 += bias[1]; a2 += bias[2]; }
        C[(size_t)wrp * 3 + 0] = a0;
        C[(size_t)wrp * 3 + 1] = a1;
        C[(size_t)wrp * 3 + 2] = a2;
    }
}

__global__ void logsoftmax_k(const float* __restrict__ X, float* __restrict__ out, int M)
{
    int i = blockIdx.x * blockDim.x + threadIdx.x;
    if (i >= M) return;
    float x0 = X[i * 3], x1 = X[i * 3 + 1], x2 = X[i * 3 + 2];
    float m = fmaxf(x0, fmaxf(x1, x2));
    float s = expf(x0 - m) + expf(x1 - m) + expf(x2 - m);
    float l = m + logf(s);
    out[i * 3] = x0 - l; out[i * 3 + 1] = x1 - l; out[i * 3 + 2] = x2 - l;
}

__global__ void prep_sw_k(const float* __restrict__ w2a, const float* __restrict__ w2b,
                          const float* __restrict__ w4, float* __restrict__ sw)
{
    if (threadIdx.x == 0 && blockIdx.x == 0) {
        {
            float m = fmaxf(w2a[0], w2a[1]);
            float e0 = expf(w2a[0] - m), e1 = expf(w2a[1] - m), s = e0 + e1;
            sw[0] = e0 / s; sw[1] = e1 / s;
        }
        {
            float m = fmaxf(w2b[0], w2b[1]);
            float e0 = expf(w2b[0] - m), e1 = expf(w2b[1] - m), s = e0 + e1;
            sw[2] = e0 / s; sw[3] = e1 / s;
        }
        {
            float m = fmaxf(fmaxf(w4[0], w4[1]), fmaxf(w4[2], w4[3]));
            float e[4]; float s = 0.f;
            for (int i = 0; i < 4; i++) { e[i] = expf(w4[i] - m); s += e[i]; }
            for (int i = 0; i < 4; i++) sw[4 + i] = e[i] / s;
        }
    }
}

// ---------------- launch ----------------
extern "C" void kernel_launch(void* const* d_in, const int* in_sizes, int n_in,
                              void* d_out, int out_size)
{
    const float* features  = (const float*)d_in[0];
    const float* adj_ori   = (const float*)d_in[1];
    const float* mp_pap    = (const float*)d_in[2];
    const float* mp_psp    = (const float*)d_in[3];
    const float* fgo_w     = (const float*)d_in[6];
    const float* fpo_w     = (const float*)d_in[7];
    const float* sgg_pap_w = (const float*)d_in[8];
    const float* sgg_psp_w = (const float*)d_in[9];
    const float* sg_agg_w  = (const float*)d_in[10];
    const float* f_agg_f_w = (const float*)d_in[11];
    const float* f_agg_w   = (const float*)d_in[12];
    const float* topo_W_a  = (const float*)d_in[13];
    const float* topo_b_a  = (const float*)d_in[14];
    const float* topo_W_s  = (const float*)d_in[15];
    const float* topo_b_s  = (const float*)d_in[16];
    const float* fgt_w_a   = (const float*)d_in[17];
    const float* fgt_w_s   = (const float*)d_in[18];
    const float* gcn_W1    = (const float*)d_in[19];
    const float* gcn_b1    = (const float*)d_in[20];
    const float* gcn_W2    = (const float*)d_in[21];
    const float* gcn_b2    = (const float*)d_in[22];

    float* arena = nullptr;
    int* iarena = nullptr;
    cudaGetSymbolAddress((void**)&arena, g_arena);
    cudaGetSymbolAddress((void**)&iarena, g_iarena);

    float* M0 = arena + OFF_M0;
    float* M1 = arena + OFF_M1;
    float* M2 = arena + OFF_M2;
    float* M3 = arena + OFF_M3;
    float* M4 = arena + OFF_M4;
    float* M5 = arena + OFF_M5;
    float* M6 = arena + OFF_M6;
    float* M7 = arena + OFF_M7;
    float* SIMS = arena + OFF_SIMS;
    float* ZT  = arena + OFF_ZT;
    float* ZPAP = arena + OFF_ZPAP;
    float* ZPSP = arena + OFF_ZPSP;
    float* ZA  = arena + OFF_ZA;
    float* ZS  = arena + OFF_ZS;
    float* ZFA = arena + OFF_ZFA;
    float* ZFS = arena + OFF_ZFS;
    float* ZSA = arena + OFF_ZSA;
    float* ZSS = arena + OFF_ZSS;
    float* FPA = arena + OFF_FPA;
    float* FPS = arena + OFF_FPS;
    float* SWA = arena + OFF_SWA;
    float* SWS = arena + OFF_SWS;
    float* THA = arena + OFF_THA;
    float* THS = arena + OFF_THS;
    float* H0B = arena + OFF_H0;
    float* X1B = arena + OFF_X1;
    float* H2B = arena + OFF_H2;
    float* X2B = arena + OFF_X2;
    float* PART = arena + OFF_PART;
    float* CPART = arena + OFF_CPART;
    float* RPART = arena + OFF_RPART;
    float* COEF = arena + OFF_COEF;
    float* DEN  = arena + OFF_DEN;
    float* SW = arena + OFF_SW;

    int* IDXA = iarena + IOFF_IDXA;
    int* IDXS = iarena + IOFF_IDXS;
    int* CNTA = iarena + IOFF_CNTA;
    int* CNTS = iarena + IOFF_CNTS;

    float* logits = (float*)d_out;
    float* out_adj = (float*)d_out + (size_t)NT_ * NCLS_;

    const float ISQH = 0.70710678118654752f; // 1/sqrt(2)

    float* CP0 = CPART + 0 * CSLOT;
    float* CP1 = CPART + 1 * CSLOT;
    float* CP2 = CPART + 2 * CSLOT;
    float* CP3 = CPART + 3 * CSLOT;
    float* CP4 = CPART + 4 * CSLOT;
    float* CP5 = CPART + 5 * CSLOT;
    float* CP6 = CPART + 6 * CSLOT;

    // Z preps round 1 — launches 1..5 so the ncu capture (-s 5 -c 1) lands on
    // the round-1 sym GEMM batch (launch 6), the dominant kernel.
    prep_z_k<<<NT_ / 8, 256>>>(features, FEAT_, NT_, fgo_w, ZT, ISQH);
    prep_z_k<<<NT_ / 8, 256>>>(mp_pap, MPD_, NT_, sgg_pap_w, ZPAP, ISQH);
    prep_z_k<<<NT_ / 8, 256>>>(mp_psp, MPD_, NT_, sgg_psp_w, ZPSP, ISQH);
    prep_z_k<<<NT_ / 8, 256>>>(features + (size_t)NT_ * FEAT_, FEAT_, NT_, fgo_w, ZA, ISQH);
    prep_z_k<<<NS_ / 8, 256>>>(features + (size_t)(NT_ + NA_) * FEAT_, FEAT_, NS_, fgo_w, ZS, ISQH);

    // round-1 sym GEMM batch: all five thresholded Z Z^T graphs in ONE launch
    {
        SymJobs jb{};
        jb.j[0] = {ZT,   M0,   CP0,     NT_, 256, 0.1f};
        jb.j[1] = {ZPAP, M1,   CP1,     NT_, 128, 0.1f};
        jb.j[2] = {ZPSP, M2,   CP2,     NT_, 128, 0.1f};
        jb.j[3] = {ZA,   M3,   nullptr, NT_, 256, 0.1f};
        jb.j[4] = {ZS,   SIMS, nullptr, NS_, 256, 0.1f};
        gemm_sym_batch_k<<<dim3(32, 32, 5), 256>>>(jb);
    }

    // scalars + CSR build + feat_prop (independent of the sym graphs)
    prep_sw_k<<<1, 32>>>(sg_agg_w, f_agg_f_w, f_agg_w, SW);
    build_csr_k<<<(NT_ * 32 + 255) / 256, 256>>>(adj_ori, NALL_, NT_, NA_, IDXA, CNTA, MAXNNZ_A);
    build_csr_k<<<(NT_ * 32 + 255) / 256, 256>>>(adj_ori, NALL_, NT_ + NA_, NS_, IDXS, CNTS, MAXNNZ_S);
    spmm_k<<<NT_, 128>>>(IDXA, CNTA, MAXNNZ_A, features + (size_t)NT_ * FEAT_, FEAT_, nullptr, FPA);
    spmm_k<<<NT_, 128>>>(IDXS, CNTS, MAXNNZ_S, features + (size_t)(NT_ + NA_) * FEAT_, FEAT_, nullptr, FPS);

    // simW = sim_r @ topo_W  (split-K=8 for occupancy), then topo_hid = ori_g @ simW + b
    gemm_nn_k<<<dim3(1, 32, 8), 256>>>(M3, topo_W_a, PART, NT_, COM_, NT_);
    reduce_split_k<<<512, 256>>>(PART, 8, (size_t)NT_ * COM_, COM_, nullptr, 0, SWA);
    gemm_nn_k<<<dim3(1, 8, 8), 256>>>(SIMS, topo_W_s, PART, NS_, COM_, NS_);
    reduce_split_k<<<128, 256>>>(PART, 8, (size_t)NS_ * COM_, COM_, nullptr, 0, SWS);
    spmm_k<<<NT_, 64>>>(IDXA, CNTA, MAXNNZ_A, SWA, COM_, topo_b_a, THA);
    spmm_k<<<NT_, 64>>>(IDXS, CNTS, MAXNNZ_S, SWS, COM_, topo_b_s, THS);

    // Z preps (round 2)
    prep_z_k<<<NT_ / 8, 256>>>(FPA, FEAT_, NT_, fpo_w, ZFA, ISQH);
    prep_z_k<<<NT_ / 8, 256>>>(FPS, FEAT_, NT_, fpo_w, ZFS, ISQH);
    prep_z_k<<<NT_ / 8, 256>>>(THA, COM_, NT_, fgt_w_a, ZSA, ISQH);
    prep_z_k<<<NT_ / 8, 256>>>(THS, COM_, NT_, fgt_w_s, ZSS, ISQH);

    // round-2 sym GEMM batch (M3 safe to overwrite: NN gemm above is ordered first)
    {
        SymJobs jb{};
        jb.j[0] = {ZFA, M3, CP3, NT_, 256, 0.2f};
        jb.j[1] = {ZFS, M4, CP4, NT_, 256, 0.2f};
        jb.j[2] = {ZSA, M5, CP5, NT_, 128, 0.1f};
        jb.j[3] = {ZSS, M6, CP6, NT_, 128, 0.1f};
        gemm_sym_batch_k<<<dim3(32, 32, 4), 256>>>(jb);
    }

    // collapsed channel attention: finalize colsums + coefficients, then ONE
    // fused 7-input combine that also emits row-sum partials
    coef_k<<<16, 256>>>(CPART, SW, COEF);
    ca7rs_k<<<dim3(32, 32, 1), 128>>>(M0, M1, M2, M3, M4, M5, M6, COEF, M7, RPART);
    denfin_k<<<16, 256>>>(RPART, COEF + 7 * NT_, DEN);

    // symmetrize + L1 column-normalize -> output adjacency (triangle blocks)
    sym_norm_tri_k<<<dim3(128, 128, 1), dim3(32, 8, 1)>>>(M7, DEN, out_adj, NT_);

    // GCN
    gemm_nn_k<<<dim3(1, 32, 1), 256>>>(features, gcn_W1, H0B, NT_, EMB_, FEAT_);
    gemm_nn_k<<<dim3(1, 32, 8), 256>>>(out_adj, H0B, PART, NT_, EMB_, NT_);
    reduce_split_k<<<512, 256>>>(PART, 8, (size_t)NT_ * EMB_, EMB_, gcn_b1, 1, X1B);
    gemm_n3_k<<<(NT_ * 32 + 255) / 256, 256>>>(X1B, gcn_W2, nullptr, H2B, NT_, EMB_);
    gemm_n3_k<<<(NT_ * 32 + 255) / 256, 256>>>(out_adj, H2B, gcn_b2, X2B, NT_, NT_);
    logsoftmax_k<<<(NT_ + 255) / 256, 256>>>(X2B, logits, NT_);
}

// round 11
// speedup vs baseline: 1.0455x; 1.0180x over previous
#include <cuda_runtime.h>
#include <math.h>

#define NT_ 4096
#define NA_ 4096
#define NS_ 1024
#define NALL_ 9216
#define FEAT_ 128
#define COM_ 64
#define MPD_ 64
#define EMB_ 64
#define NCLS_ 3

constexpr size_t MAT = (size_t)NT_ * NT_;

// ---------------- arena layout (floats) ----------------
constexpr size_t OFF_M0   = 0;              // G_targ
constexpr size_t OFF_M1   = OFF_M0 + MAT;   // SEM_pap
constexpr size_t OFF_M2   = OFF_M1 + MAT;   // SEM_psp
constexpr size_t OFF_M3   = OFF_M2 + MAT;   // SIM_a -> F_a
constexpr size_t OFF_M4   = OFF_M3 + MAT;   // F_s
constexpr size_t OFF_M5   = OFF_M4 + MAT;   // S_a
constexpr size_t OFF_M6   = OFF_M5 + MAT;   // S_s
constexpr size_t OFF_M7   = OFF_M6 + MAT;   // new_adj (pre-symmetrize)
constexpr size_t OFF_SIMS = OFF_M7 + MAT;                    // sim_r_s 1024x1024
constexpr size_t OFF_ZT   = OFF_SIMS + (size_t)NS_ * NS_;    // 4096x256
constexpr size_t OFF_ZPAP = OFF_ZT   + (size_t)NT_ * 256;    // 4096x128
constexpr size_t OFF_ZPSP = OFF_ZPAP + (size_t)NT_ * 128;
constexpr size_t OFF_ZA   = OFF_ZPSP + (size_t)NT_ * 128;    // 4096x256
constexpr size_t OFF_ZS   = OFF_ZA   + (size_t)NT_ * 256;    // 1024x256
constexpr size_t OFF_ZFA  = OFF_ZS   + (size_t)NS_ * 256;    // 4096x256
constexpr size_t OFF_ZFS  = OFF_ZFA  + (size_t)NT_ * 256;
constexpr size_t OFF_ZSA  = OFF_ZFS  + (size_t)NT_ * 256;    // 4096x128
constexpr size_t OFF_ZSS  = OFF_ZSA  + (size_t)NT_ * 128;
constexpr size_t OFF_FPA  = OFF_ZSS  + (size_t)NT_ * 128;    // feat_prop_a 4096x128
constexpr size_t OFF_FPS  = OFF_FPA  + (size_t)NT_ * FEAT_;
constexpr size_t OFF_SWA  = OFF_FPS  + (size_t)NT_ * FEAT_;  // simW_a 4096x64
constexpr size_t OFF_SWS  = OFF_SWA  + (size_t)NT_ * COM_;   // simW_s 1024x64
constexpr size_t OFF_THA  = OFF_SWS  + (size_t)NS_ * COM_;   // topo_hid_a
constexpr size_t OFF_THS  = OFF_THA  + (size_t)NT_ * COM_;
constexpr size_t OFF_H0   = OFF_THS  + (size_t)NT_ * COM_;   // 4096x64
constexpr size_t OFF_X1   = OFF_H0   + (size_t)NT_ * EMB_;   // 4096x64
constexpr size_t OFF_H2   = OFF_X1   + (size_t)NT_ * EMB_;   // 4096x3
constexpr size_t OFF_X2   = OFF_H2   + (size_t)NT_ * NCLS_;  // 4096x3
constexpr size_t OFF_PART = OFF_X2   + (size_t)NT_ * NCLS_;  // split-K partials 8x4096x64
constexpr size_t OFF_CPART= OFF_PART + (size_t)8 * NT_ * 64; // colsum partials 7 slots x 32 x 4096
constexpr size_t CSLOT    = (size_t)32 * NT_;
constexpr size_t OFF_RPART= OFF_CPART + (size_t)7 * CSLOT;   // ca7 rowsum partials 32 x 4096
constexpr size_t OFF_COEF = OFF_RPART + CSLOT;               // c0..c6, cs_na (8 x NT_)
constexpr size_t OFF_DEN  = OFF_COEF + (size_t)8 * NT_;      // fmax(cs_na+rs_na, eps)
constexpr size_t OFF_SW   = OFF_DEN + NT_;                   // softmaxed channel weights (8)
constexpr size_t ARENA_SZ = OFF_SW + 8;

__device__ float g_arena[ARENA_SZ];

constexpr int MAXNNZ_A = 512;
constexpr int MAXNNZ_S = 256;
constexpr size_t IOFF_IDXA = 0;
constexpr size_t IOFF_IDXS = IOFF_IDXA + (size_t)NT_ * MAXNNZ_A;
constexpr size_t IOFF_CNTA = IOFF_IDXS + (size_t)NT_ * MAXNNZ_S;
constexpr size_t IOFF_CNTS = IOFF_CNTA + NT_;
constexpr size_t IARENA_SZ = IOFF_CNTS + NT_;
__device__ int g_iarena[IARENA_SZ];

// ---------------- persistent batched symmetric thresholded syrk ----------------
// Work list = concatenated upper-triangle 128x128 tiles of each job.
// Blocks stride the item list (grid 296 ~= 2 CTAs/SM x 148): no wave-quantized
// tail, just <=1-item skew. Each item: C = thresh(A A^T) tile + mirror, with
// optional fused column-L1 partials (single writer per (slice,col) -> deterministic).
struct SymJob {
    const float* A;
    float* C;
    float* cpart;   // nullptr -> no colsum partials
    int n;
    int K;
    float th;
};
struct SymJobs {
    SymJob j[5];
    int base[6];    // cumulative item counts
    int njobs;
    int total;
};

__global__ __launch_bounds__(256)
void gemm_sym_persist_k(SymJobs jobs)
{
    __shared__ float As[2][8][128];
    __shared__ float Bs[2][8][128];
    __shared__ float Red2[128 * 17];

    const int tid = threadIdx.x;
    const int tx = tid & 15, ty = tid >> 4;
    const int lr = tid >> 1;           // 0..127
    const int lc = (tid & 1) << 2;     // 0,4

    for (int item = blockIdx.x; item < jobs.total; item += gridDim.x) {
        __syncthreads();   // protect smem reuse across items

        // decode job + upper-triangle tile coords
        int ji = 0;
        while (item >= jobs.base[ji + 1]) ji++;
        const SymJob job = jobs.j[ji];
        const int nb = job.n >> 7;
        int t = item - jobs.base[ji];
        int by = 0;
        while (true) { int len = nb - by; if (t < len) break; t -= len; by++; }
        const int bx = by + t;

        const int row0 = by * 128, col0 = bx * 128;
        const int N = job.n, K = job.K;
        const float th = job.th;
        const float* __restrict__ A = job.A;
        float* __restrict__ C = job.C;

        float acc[8][8];
#pragma unroll
        for (int i = 0; i < 8; i++)
#pragma unroll
            for (int j = 0; j < 8; j++) acc[i][j] = 0.f;

        float4 av, bv;
        auto ldg_tile = [&](int k0) {
            av = *reinterpret_cast<const float4*>(A + (size_t)(row0 + lr) * K + k0 + lc);
            bv = *reinterpret_cast<const float4*>(A + (size_t)(col0 + lr) * K + k0 + lc);
        };
        auto sts_tile = [&](int b) {
            As[b][lc + 0][lr] = av.x; As[b][lc + 1][lr] = av.y;
            As[b][lc + 2][lr] = av.z; As[b][lc + 3][lr] = av.w;
            Bs[b][lc + 0][lr] = bv.x; Bs[b][lc + 1][lr] = bv.y;
            Bs[b][lc + 2][lr] = bv.z; Bs[b][lc + 3][lr] = bv.w;
        };

        ldg_tile(0);
        sts_tile(0);
        __syncthreads();

        int buf = 0;
        for (int k0 = 0; k0 < K; k0 += 8) {
            const bool more = (k0 + 8) < K;
            if (more) ldg_tile(k0 + 8);
#pragma unroll
            for (int kk = 0; kk < 8; kk++) {
                float af[8], bf[8];
                *reinterpret_cast<float4*>(af)     = *reinterpret_cast<const float4*>(&As[buf][kk][ty * 8]);
                *reinterpret_cast<float4*>(af + 4) = *reinterpret_cast<const float4*>(&As[buf][kk][ty * 8 + 4]);
                *reinterpret_cast<float4*>(bf)     = *reinterpret_cast<const float4*>(&Bs[buf][kk][tx * 8]);
                *reinterpret_cast<float4*>(bf + 4) = *reinterpret_cast<const float4*>(&Bs[buf][kk][tx * 8 + 4]);
#pragma unroll
                for (int i = 0; i < 8; i++)
#pragma unroll
                    for (int j = 0; j < 8; j++)
                        acc[i][j] += af[i] * bf[j];
            }
            if (more) sts_tile(buf ^ 1);
            __syncthreads();
            buf ^= 1;
        }

        // threshold in-register, write original tile, accumulate colsum partials
        float csum[8];
#pragma unroll
        for (int j = 0; j < 8; j++) csum[j] = 0.f;

#pragma unroll
        for (int i = 0; i < 8; i++) {
            int r = row0 + ty * 8 + i;
#pragma unroll
            for (int j = 0; j < 8; j++) {
                float v = acc[i][j];
                if (v < th) v = 0.f;
                acc[i][j] = v;
                csum[j] += v;   // entries nonneg after threshold (th > 0)
                C[(size_t)r * N + col0 + tx * 8 + j] = v;
            }
        }

        const bool do_csum = (job.cpart != nullptr);
        if (do_csum) {
            // reuse As as a [16][128] reduction buffer (mainloop done, As dead)
            float* red = &As[0][0][0];
#pragma unroll
            for (int j = 0; j < 8; j++) red[ty * 128 + tx * 8 + j] = csum[j];
            __syncthreads();
            if (tid < 128) {
                float s = 0.f;
#pragma unroll
                for (int t2 = 0; t2 < 16; t2++) s += red[t2 * 128 + tid];
                job.cpart[(size_t)by * N + col0 + tid] = s;
            }
        }

        if (bx > by) {
            // mirror write: C[c][r]; per-thread 8 consecutive r -> 32B sectors
#pragma unroll
            for (int j = 0; j < 8; j++) {
                int c = col0 + tx * 8 + j;
                float t0[4] = {acc[0][j], acc[1][j], acc[2][j], acc[3][j]};
                float t1[4] = {acc[4][j], acc[5][j], acc[6][j], acc[7][j]};
                size_t base = (size_t)c * N + row0 + ty * 8;
                *reinterpret_cast<float4*>(&C[base])     = *reinterpret_cast<float4*>(t0);
                *reinterpret_cast<float4*>(&C[base + 4]) = *reinterpret_cast<float4*>(t1);
            }
            if (do_csum) {
                // mirror colsum: column (row0+ty*8+i), partial = sum_j acc[i][j]
                __syncthreads();
#pragma unroll
                for (int i = 0; i < 8; i++) {
                    float s = 0.f;
#pragma unroll
                    for (int j = 0; j < 8; j++) s += acc[i][j];
                    Red2[(ty * 8 + i) * 17 + tx] = s;
                }
                __syncthreads();
                if (tid < 128) {
                    float s = 0.f;
#pragma unroll
                    for (int t2 = 0; t2 < 16; t2++) s += Red2[tid * 17 + t2];
                    job.cpart[(size_t)bx * N + row0 + tid] = s;
                }
            }
        }
    }
}

// ---------------- plain NN GEMM (128x128 tile, split-K via gridDim.z) ----------------
__global__ __launch_bounds__(256)
void gemm_nn_k(const float* __restrict__ A, const float* __restrict__ B,
               float* __restrict__ C, int M, int N, int K)
{
    __shared__ float As[2][8][128];
    __shared__ float Bs[2][8][128];
    const int tid = threadIdx.x;
    const int tx = tid & 15, ty = tid >> 4;
    const int row0 = blockIdx.y * 128, col0 = blockIdx.x * 128;

    const int klen = K / gridDim.z;
    const int kbeg = blockIdx.z * klen;
    const int kend = kbeg + klen;
    C += (size_t)blockIdx.z * (size_t)M * N;

    float acc[8][8];
#pragma unroll
    for (int i = 0; i < 8; i++)
#pragma unroll
        for (int j = 0; j < 8; j++) acc[i][j] = 0.f;

    const int lr  = tid >> 1;
    const int lc  = (tid & 1) << 2;
    const int bnr = tid >> 5;
    const int bnc = (tid & 31) << 2;

    float4 av, bv;
    auto ldg_tile = [&](int k0) {
        av = make_float4(0.f, 0.f, 0.f, 0.f);
        {
            int r = row0 + lr;
            if (r < M) av = *reinterpret_cast<const float4*>(A + (size_t)r * K + k0 + lc);
        }
        bv = make_float4(0.f, 0.f, 0.f, 0.f);
        {
            int c = col0 + bnc;
            if (c + 3 < N) bv = *reinterpret_cast<const float4*>(B + (size_t)(k0 + bnr) * N + c);
        }
    };
    auto sts_tile = [&](int b) {
        As[b][lc + 0][lr] = av.x; As[b][lc + 1][lr] = av.y;
        As[b][lc + 2][lr] = av.z; As[b][lc + 3][lr] = av.w;
        *reinterpret_cast<float4*>(&Bs[b][bnr][bnc]) = bv;
    };

    ldg_tile(kbeg);
    sts_tile(0);
    __syncthreads();

    int buf = 0;
    for (int k0 = kbeg; k0 < kend; k0 += 8) {
        const bool more = (k0 + 8) < kend;
        if (more) ldg_tile(k0 + 8);
#pragma unroll
        for (int kk = 0; kk < 8; kk++) {
            float af[8], bf[8];
            *reinterpret_cast<float4*>(af)     = *reinterpret_cast<const float4*>(&As[buf][kk][ty * 8]);
            *reinterpret_cast<float4*>(af + 4) = *reinterpret_cast<const float4*>(&As[buf][kk][ty * 8 + 4]);
            *reinterpret_cast<float4*>(bf)     = *reinterpret_cast<const float4*>(&Bs[buf][kk][tx * 8]);
            *reinterpret_cast<float4*>(bf + 4) = *reinterpret_cast<const float4*>(&Bs[buf][kk][tx * 8 + 4]);
#pragma unroll
            for (int i = 0; i < 8; i++)
#pragma unroll
                for (int j = 0; j < 8; j++)
                    acc[i][j] += af[i] * bf[j];
        }
        if (more) sts_tile(buf ^ 1);
        __syncthreads();
        buf ^= 1;
    }
#pragma unroll
    for (int i = 0; i < 8; i++) {
        int r = row0 + ty * 8 + i;
        if (r >= M) continue;
#pragma unroll
        for (int j = 0; j < 8; j++) {
            int c = col0 + tx * 8 + j;
            if (c >= N) continue;
            C[(size_t)r * N + c] = acc[i][j];
        }
    }
}

// reduce split-K partials: out[e] = sum_z part[z*mn+e] (+bias[e%N]) (relu?)
__global__ void reduce_split_k(const float* __restrict__ part, int splits, size_t mn,
                               int N, const float* __restrict__ bias, int relu,
                               float* __restrict__ out)
{
    for (size_t e = (size_t)blockIdx.x * blockDim.x + threadIdx.x; e < mn;
         e += (size_t)gridDim.x * blockDim.x) {
        float s = 0.f;
        for (int z = 0; z < splits; z++) s += part[(size_t)z * mn + e];
        if (bias) s += bias[(int)(e % N)];
        if (relu) s = fmaxf(s, 0.f);
        out[e] = s;
    }
}

// ---------------- batched Z prep (warp-per-row, both heads fused) ----------------
// Same arithmetic as round-10 prep_z (frozen to keep rel_err stable); multiple
// jobs in one launch, warp -> job decode via cumulative row bases.
struct PZJob { const float* X; float* Z; const float* w; int d; };
struct PZJobs { PZJob j[5]; int base[6]; int njobs; };

__global__ void pz_batch_k(PZJobs jb, float invsqH)
{
    int wrp = (blockIdx.x * blockDim.x + threadIdx.x) >> 5;
    int lane = threadIdx.x & 31;
    if (wrp >= jb.base[jb.njobs]) return;
    int ji = 0;
    while (wrp >= jb.base[ji + 1]) ji++;
    const PZJob job = jb.j[ji];
    int row = wrp - jb.base[ji];
    const int d = job.d;
    const float* xr = job.X + (size_t)row * d;
    const float* w = job.w;
    int nper = d >> 5;   // 2 or 4
    float v0[4], v1[4];
    float s0 = 0.f, s1 = 0.f;
#pragma unroll 4
    for (int i = 0; i < nper; i++) {
        int c = lane + 32 * i;
        float x = xr[c];
        float a = x * __ldg(&w[c]);
        float b = x * __ldg(&w[d + c]);
        v0[i] = a; v1[i] = b;
        s0 += a * a; s1 += b * b;
    }
#pragma unroll
    for (int o = 16; o > 0; o >>= 1) {
        s0 += __shfl_xor_sync(0xffffffffu, s0, o);
        s1 += __shfl_xor_sync(0xffffffffu, s1, o);
    }
    float n0 = invsqH / fmaxf(sqrtf(s0), 1e-12f);
    float n1 = invsqH / fmaxf(sqrtf(s1), 1e-12f);
    float* zr = job.Z + (size_t)row * 2 * d;
#pragma unroll 4
    for (int i = 0; i < nper; i++) {
        int c = lane + 32 * i;
        zr[c] = v0[i] * n0;
        zr[d + c] = v1[i] * n1;
    }
}

// ---------------- CSR build (deterministic ballot-compaction, warp/row) ----------------
__global__ void build_csr_k(const float* __restrict__ adj, int ld, int coloff, int ncols,
                            int* __restrict__ idx, int* __restrict__ cnt, int maxnnz)
{
    int wrp = (blockIdx.x * blockDim.x + threadIdx.x) >> 5;
    int lane = threadIdx.x & 31;
    if (wrp >= NT_) return;
    const float* rowp = adj + (size_t)wrp * ld + coloff;
    int base = 0;
    for (int j0 = 0; j0 < ncols; j0 += 32) {
        float v = rowp[j0 + lane];
        unsigned m = __ballot_sync(0xffffffffu, v != 0.f);
        if (v != 0.f) {
            int r = __popc(m & ((1u << lane) - 1u));
            int p = base + r;
            if (p < maxnnz) idx[(size_t)wrp * maxnnz + p] = j0 + lane;
        }
        base += __popc(m);
    }
    if (lane == 0) cnt[wrp] = base < maxnnz ? base : maxnnz;
}

// ---------------- SpMM: out[i,:] = sum_{k in nnz(i)} B[k,:] (+bias) ----------------
__global__ void spmm_k(const int* __restrict__ idx, const int* __restrict__ cnt, int maxnnz,
                       const float* __restrict__ B, int ncols,
                       const float* __restrict__ bias, float* __restrict__ out)
{
    int row = blockIdx.x;
    int j = threadIdx.x;
    int c = cnt[row];
    const int* ip = idx + (size_t)row * maxnnz;
    float acc = bias ? bias[j] : 0.f;
    for (int t = 0; t < c; t++) {
        int r = __ldg(&ip[t]);
        acc += B[(size_t)r * ncols + j];
    }
    out[(size_t)row * ncols + j] = acc;
}

// ---------------- collapsed channel-attention coefficients ----------------
__global__ void coef_k(const float* __restrict__ cpart, const float* __restrict__ sw,
                       float* __restrict__ coef)
{
    int j = blockIdx.x * blockDim.x + threadIdx.x;
    if (j >= NT_) return;
    float cs[7];
#pragma unroll
    for (int k = 0; k < 7; k++) {
        const float* p = cpart + (size_t)k * CSLOT + j;
        float s = 0.f;
#pragma unroll
        for (int z = 0; z < 32; z++) s += p[(size_t)z * NT_];
        cs[k] = s;
    }
    float g0 = sw[0], g1 = sw[1], f0 = sw[2], f1 = sw[3];
    float v0 = sw[4], v1 = sw[5], v2 = sw[6], v3 = sw[7];
    const float eps = 1e-12f;
    float csem = g0 * (cs[1] > 0.f ? 1.f : 0.f) + g1 * (cs[2] > 0.f ? 1.f : 0.f);
    float cfp  = f0 * (cs[3] > 0.f ? 1.f : 0.f) + f1 * (cs[4] > 0.f ? 1.f : 0.f);
    float ctt  = f0 * (cs[5] > 0.f ? 1.f : 0.f) + f1 * (cs[6] > 0.f ? 1.f : 0.f);
    float ksem = v1 / fmaxf(csem, eps);
    float kfp  = v2 / fmaxf(cfp, eps);
    float ktt  = v3 / fmaxf(ctt, eps);
    float c[7];
    c[0] = v0 / fmaxf(cs[0], eps);
    c[1] = ksem * g0 / fmaxf(cs[1], eps);
    c[2] = ksem * g1 / fmaxf(cs[2], eps);
    c[3] = kfp * f0 / fmaxf(cs[3], eps);
    c[4] = kfp * f1 / fmaxf(cs[4], eps);
    c[5] = ktt * f0 / fmaxf(cs[5], eps);
    c[6] = ktt * f1 / fmaxf(cs[6], eps);
    float cna = 0.f;
#pragma unroll
    for (int k = 0; k < 7; k++) {
        coef[(size_t)k * NT_ + j] = c[k];
        cna += c[k] * cs[k];
    }
    coef[(size_t)7 * NT_ + j] = cna;   // cs_na
}

// ---------------- fused 7-channel combine + row-sum partials ----------------
__global__ void ca7rs_k(const float* __restrict__ M0, const float* __restrict__ M1,
                        const float* __restrict__ M2, const float* __restrict__ M3,
                        const float* __restrict__ M4, const float* __restrict__ M5,
                        const float* __restrict__ M6,
                        const float* __restrict__ coef, float* __restrict__ out,
                        float* __restrict__ rpart)
{
    __shared__ float sh[8][129];
    __shared__ float sh2[8][16];
    int tid = threadIdx.x;
    int j = blockIdx.x * 128 + tid;
    int r0 = blockIdx.y * 128;
    float c0 = coef[0 * NT_ + j], c1 = coef[1 * NT_ + j], c2 = coef[2 * NT_ + j];
    float c3 = coef[3 * NT_ + j], c4 = coef[4 * NT_ + j];
    float c5 = coef[5 * NT_ + j], c6 = coef[6 * NT_ + j];
    int g = tid & 15, rr2 = tid >> 4;   // reduction role: lane-group, row
    for (int ch = 0; ch < 16; ch++) {
        int rbase = r0 + ch * 8;
#pragma unroll
        for (int rr = 0; rr < 8; rr++) {
            size_t e = (size_t)(rbase + rr) * NT_ + j;
            float v = c0 * M0[e] + c1 * M1[e] + c2 * M2[e] + c3 * M3[e]
                    + c4 * M4[e] + c5 * M5[e] + c6 * M6[e];
            out[e] = v;
            sh[rr][tid] = v;
        }
        __syncthreads();
        {
            float s = 0.f;
#pragma unroll
            for (int t = 0; t < 8; t++) s += sh[rr2][g * 8 + t];
            sh2[rr2][g] = s;
        }
        __syncthreads();
        if (tid < 8) {
            float s = 0.f;
#pragma unroll
            for (int t = 0; t < 16; t++) s += sh2[tid][t];
            rpart[(size_t)blockIdx.x * NT_ + rbase + tid] = s;
        }
        __syncthreads();
    }
}

// finalize denominator: den[r] = fmax(cs_na[r] + sum_z rpart[z][r], eps)
__global__ void denfin_k(const float* __restrict__ rpart, const float* __restrict__ cna,
                         float* __restrict__ den)
{
    int r = blockIdx.x * blockDim.x + threadIdx.x;
    if (r >= NT_) return;
    float s = 0.f;
#pragma unroll
    for (int z = 0; z < 32; z++) s += rpart[(size_t)z * NT_ + r];
    den[r] = fmaxf(cna[r] + s, 1e-12f);
}

// ---------------- symmetrize + column-L1 normalize (triangle blocks) ----------------
__global__ void sym_norm_tri_k(const float* __restrict__ A, const float* __restrict__ den,
                               float* __restrict__ out, int n)
{
    if ((int)blockIdx.x < (int)blockIdx.y) return;
    __shared__ float T1[32][33];
    __shared__ float T2[32][33];
    int I = blockIdx.y * 32, J = blockIdx.x * 32;
    for (int r = threadIdx.y; r < 32; r += 8) {
        T1[r][threadIdx.x] = A[(size_t)(I + r) * n + J + threadIdx.x];
        T2[r][threadIdx.x] = A[(size_t)(J + r) * n + I + threadIdx.x];
    }
    __syncthreads();
    for (int r = threadIdx.y; r < 32; r += 8) {
        int j = J + threadIdx.x;
        out[(size_t)(I + r) * n + j] = (T1[r][threadIdx.x] + T2[threadIdx.x][r]) / den[j];
    }
    if (blockIdx.x > blockIdx.y) {
        for (int r = threadIdx.y; r < 32; r += 8) {
            int j = I + threadIdx.x;
            out[(size_t)(J + r) * n + j] = (T2[r][threadIdx.x] + T1[threadIdx.x][r]) / den[j];
        }
    }
}

// ---------------- small-N (N=3) GEMM, warp/row ----------------
__global__ void gemm_n3_k(const float* __restrict__ A, const float* __restrict__ B,
                          const float* __restrict__ bias, float* __restrict__ C,
                          int M, int K)
{
    int wrp = (blockIdx.x * blockDim.x + threadIdx.x) >> 5;
    int lane = threadIdx.x & 31;
    if (wrp >= M) return;
    const float* row = A + (size_t)wrp * K;
    float a0 = 0.f, a1 = 0.f, a2 = 0.f;
    for (int k = lane; k < K; k += 32) {
        float a = row[k];
        a0 += a * __ldg(&B[k * 3 + 0]);
        a1 += a * __ldg(&B[k * 3 + 1]);
        a2 += a * __ldg(&B[k * 3 + 2]);
    }
    for (int o = 16; o > 0; o >>= 1) {
        a0 += __shfl_down_sync(0xffffffffu, a0, o);
        a1 += __shfl_down_sync(0xffffffffu, a1, o);
        a2 += __shfl_down_sync(0xffffffffu, a2, o);
    }
    if (lane == 0) {
        if (bias) { a0 += bias[0]; a1 += bias[1]; a2 += bias[2]; }
        C[(size_t)wrp * 3 + 0] = a0;
        C[(size_t)wrp * 3 + 1] = a1;
        C[(size_t)wrp * 3 + 2] = a2;
    }
}

__global__ void logsoftmax_k(const float* __restrict__ X, float* __restrict__ out, int M)
{
    int i = blockIdx.x * blockDim.x + threadIdx.x;
    if (i >= M) return;
    float x0 = X[i * 3], x1 = X[i * 3 + 1], x2 = X[i * 3 + 2];
    float m = fmaxf(x0, fmaxf(x1, x2));
    float s = expf(x0 - m) + expf(x1 - m) + expf(x2 - m);
    float l = m + logf(s);
    out[i * 3] = x0 - l; out[i * 3 + 1] = x1 - l; out[i * 3 + 2] = x2 - l;
}

__global__ void prep_sw_k(const float* __restrict__ w2a, const float* __restrict__ w2b,
                          const float* __restrict__ w4, float* __restrict__ sw)
{
    if (threadIdx.x == 0 && blockIdx.x == 0) {
        {
            float m = fmaxf(w2a[0], w2a[1]);
            float e0 = expf(w2a[0] - m), e1 = expf(w2a[1] - m), s = e0 + e1;
            sw[0] = e0 / s; sw[1] = e1 / s;
        }
        {
            float m = fmaxf(w2b[0], w2b[1]);
            float e0 = expf(w2b[0] - m), e1 = expf(w2b[1] - m), s = e0 + e1;
            sw[2] = e0 / s; sw[3] = e1 / s;
        }
        {
            float m = fmaxf(fmaxf(w4[0], w4[1]), fmaxf(w4[2], w4[3]));
            float e[4]; float s = 0.f;
            for (int i = 0; i < 4; i++) { e[i] = expf(w4[i] - m); s += e[i]; }
            for (int i = 0; i < 4; i++) sw[4 + i] = e[i] / s;
        }
    }
}

// ---------------- launch ----------------
extern "C" void kernel_launch(void* const* d_in, const int* in_sizes, int n_in,
                              void* d_out, int out_size)
{
    const float* features  = (const float*)d_in[0];
    const float* adj_ori   = (const float*)d_in[1];
    const float* mp_pap    = (const float*)d_in[2];
    const float* mp_psp    = (const float*)d_in[3];
    const float* fgo_w     = (const float*)d_in[6];
    const float* fpo_w     = (const float*)d_in[7];
    const float* sgg_pap_w = (const float*)d_in[8];
    const float* sgg_psp_w = (const float*)d_in[9];
    const float* sg_agg_w  = (const float*)d_in[10];
    const float* f_agg_f_w = (const float*)d_in[11];
    const float* f_agg_w   = (const float*)d_in[12];
    const float* topo_W_a  = (const float*)d_in[13];
    const float* topo_b_a  = (const float*)d_in[14];
    const float* topo_W_s  = (const float*)d_in[15];
    const float* topo_b_s  = (const float*)d_in[16];
    const float* fgt_w_a   = (const float*)d_in[17];
    const float* fgt_w_s   = (const float*)d_in[18];
    const float* gcn_W1    = (const float*)d_in[19];
    const float* gcn_b1    = (const float*)d_in[20];
    const float* gcn_W2    = (const float*)d_in[21];
    const float* gcn_b2    = (const float*)d_in[22];

    float* arena = nullptr;
    int* iarena = nullptr;
    cudaGetSymbolAddress((void**)&arena, g_arena);
    cudaGetSymbolAddress((void**)&iarena, g_iarena);

    float* M0 = arena + OFF_M0;
    float* M1 = arena + OFF_M1;
    float* M2 = arena + OFF_M2;
    float* M3 = arena + OFF_M3;
    float* M4 = arena + OFF_M4;
    float* M5 = arena + OFF_M5;
    float* M6 = arena + OFF_M6;
    float* M7 = arena + OFF_M7;
    float* SIMS = arena + OFF_SIMS;
    float* ZT  = arena + OFF_ZT;
    float* ZPAP = arena + OFF_ZPAP;
    float* ZPSP = arena + OFF_ZPSP;
    float* ZA  = arena + OFF_ZA;
    float* ZS  = arena + OFF_ZS;
    float* ZFA = arena + OFF_ZFA;
    float* ZFS = arena + OFF_ZFS;
    float* ZSA = arena + OFF_ZSA;
    float* ZSS = arena + OFF_ZSS;
    float* FPA = arena + OFF_FPA;
    float* FPS = arena + OFF_FPS;
    float* SWA = arena + OFF_SWA;
    float* SWS = arena + OFF_SWS;
    float* THA = arena + OFF_THA;
    float* THS = arena + OFF_THS;
    float* H0B = arena + OFF_H0;
    float* X1B = arena + OFF_X1;
    float* H2B = arena + OFF_H2;
    float* X2B = arena + OFF_X2;
    float* PART = arena + OFF_PART;
    float* CPART = arena + OFF_CPART;
    float* RPART = arena + OFF_RPART;
    float* COEF = arena + OFF_COEF;
    float* DEN  = arena + OFF_DEN;
    float* SW = arena + OFF_SW;

    int* IDXA = iarena + IOFF_IDXA;
    int* IDXS = iarena + IOFF_IDXS;
    int* CNTA = iarena + IOFF_CNTA;
    int* CNTS = iarena + IOFF_CNTS;

    float* logits = (float*)d_out;
    float* out_adj = (float*)d_out + (size_t)NT_ * NCLS_;

    const float ISQH = 0.70710678118654752f; // 1/sqrt(2)

    float* CP0 = CPART + 0 * CSLOT;
    float* CP1 = CPART + 1 * CSLOT;
    float* CP2 = CPART + 2 * CSLOT;
    float* CP3 = CPART + 3 * CSLOT;
    float* CP4 = CPART + 4 * CSLOT;
    float* CP5 = CPART + 5 * CSLOT;
    float* CP6 = CPART + 6 * CSLOT;

    const int PERSIST_GRID = 296;   // ~2 CTAs/SM x 148 SMs

    // L1: all round-1 Z preps in ONE batched launch
    {
        PZJobs pz{};
        pz.j[0] = {features, ZT, fgo_w, FEAT_};
        pz.j[1] = {mp_pap, ZPAP, sgg_pap_w, MPD_};
        pz.j[2] = {mp_psp, ZPSP, sgg_psp_w, MPD_};
        pz.j[3] = {features + (size_t)NT_ * FEAT_, ZA, fgo_w, FEAT_};
        pz.j[4] = {features + (size_t)(NT_ + NA_) * FEAT_, ZS, fgo_w, FEAT_};
        pz.base[0] = 0; pz.base[1] = NT_; pz.base[2] = 2 * NT_;
        pz.base[3] = 3 * NT_; pz.base[4] = 4 * NT_; pz.base[5] = 4 * NT_ + NS_;
        pz.njobs = 5;
        pz_batch_k<<<(pz.base[5] * 32 + 255) / 256, 256>>>(pz, ISQH);
    }

    // L2, L3: CSR builds (independent of Z)
    build_csr_k<<<(NT_ * 32 + 255) / 256, 256>>>(adj_ori, NALL_, NT_, NA_, IDXA, CNTA, MAXNNZ_A);
    build_csr_k<<<(NT_ * 32 + 255) / 256, 256>>>(adj_ori, NALL_, NT_ + NA_, NS_, IDXS, CNTS, MAXNNZ_S);

    // L4: round-1 persistent sym GEMM batch  (ncu -s5 -c1 + 2 hidden harness
    // launches => this is the captured launch)
    {
        SymJobs jb{};
        jb.j[0] = {ZT,   M0,   CP0,     NT_, 256, 0.1f};
        jb.j[1] = {ZPAP, M1,   CP1,     NT_, 128, 0.1f};
        jb.j[2] = {ZPSP, M2,   CP2,     NT_, 128, 0.1f};
        jb.j[3] = {ZA,   M3,   nullptr, NT_, 256, 0.1f};
        jb.j[4] = {ZS,   SIMS, nullptr, NS_, 256, 0.1f};
        jb.base[0] = 0; jb.base[1] = 528; jb.base[2] = 1056;
        jb.base[3] = 1584; jb.base[4] = 2112; jb.base[5] = 2148;
        jb.njobs = 5; jb.total = 2148;
        gemm_sym_persist_k<<<PERSIST_GRID, 256>>>(jb);
    }

    // scalars + feat_prop
    prep_sw_k<<<1, 32>>>(sg_agg_w, f_agg_f_w, f_agg_w, SW);
    spmm_k<<<NT_, 128>>>(IDXA, CNTA, MAXNNZ_A, features + (size_t)NT_ * FEAT_, FEAT_, nullptr, FPA);
    spmm_k<<<NT_, 128>>>(IDXS, CNTS, MAXNNZ_S, features + (size_t)(NT_ + NA_) * FEAT_, FEAT_, nullptr, FPS);

    // simW = sim_r @ topo_W  (split-K=8 for occupancy), then topo_hid = ori_g @ simW + b
    gemm_nn_k<<<dim3(1, 32, 8), 256>>>(M3, topo_W_a, PART, NT_, COM_, NT_);
    reduce_split_k<<<512, 256>>>(PART, 8, (size_t)NT_ * COM_, COM_, nullptr, 0, SWA);
    gemm_nn_k<<<dim3(1, 8, 8), 256>>>(SIMS, topo_W_s, PART, NS_, COM_, NS_);
    reduce_split_k<<<128, 256>>>(PART, 8, (size_t)NS_ * COM_, COM_, nullptr, 0, SWS);
    spmm_k<<<NT_, 64>>>(IDXA, CNTA, MAXNNZ_A, SWA, COM_, topo_b_a, THA);
    spmm_k<<<NT_, 64>>>(IDXS, CNTS, MAXNNZ_S, SWS, COM_, topo_b_s, THS);

    // round-2 Z preps in ONE batched launch
    {
        PZJobs pz{};
        pz.j[0] = {FPA, ZFA, fpo_w, FEAT_};
        pz.j[1] = {FPS, ZFS, fpo_w, FEAT_};
        pz.j[2] = {THA, ZSA, fgt_w_a, COM_};
        pz.j[3] = {THS, ZSS, fgt_w_s, COM_};
        pz.base[0] = 0; pz.base[1] = NT_; pz.base[2] = 2 * NT_;
        pz.base[3] = 3 * NT_; pz.base[4] = 4 * NT_; pz.base[5] = 4 * NT_;
        pz.njobs = 4;
        pz_batch_k<<<(pz.base[4] * 32 + 255) / 256, 256>>>(pz, ISQH);
    }

    // round-2 persistent sym GEMM batch (M3 safe: NN gemm above ordered first)
    {
        SymJobs jb{};
        jb.j[0] = {ZFA, M3, CP3, NT_, 256, 0.2f};
        jb.j[1] = {ZFS, M4, CP4, NT_, 256, 0.2f};
        jb.j[2] = {ZSA, M5, CP5, NT_, 128, 0.1f};
        jb.j[3] = {ZSS, M6, CP6, NT_, 128, 0.1f};
        jb.base[0] = 0; jb.base[1] = 528; jb.base[2] = 1056;
        jb.base[3] = 1584; jb.base[4] = 2112; jb.base[5] = 2112;
        jb.njobs = 4; jb.total = 2112;
        gemm_sym_persist_k<<<PERSIST_GRID, 256>>>(jb);
    }

    // collapsed channel attention: finalize colsums + coefficients, then ONE
    // fused 7-input combine that also emits row-sum partials
    coef_k<<<16, 256>>>(CPART, SW, COEF);
    ca7rs_k<<<dim3(32, 32, 1), 128>>>(M0, M1, M2, M3, M4, M5, M6, COEF, M7, RPART);
    denfin_k<<<16, 256>>>(RPART, COEF + 7 * NT_, DEN);

    // symmetrize + L1 column-normalize -> output adjacency (triangle blocks)
    sym_norm_tri_k<<<dim3(128, 128, 1), dim3(32, 8, 1)>>>(M7, DEN, out_adj, NT_);

    // GCN
    gemm_nn_k<<<dim3(1, 32, 1), 256>>>(features, gcn_W1, H0B, NT_, EMB_, FEAT_);
    gemm_nn_k<<<dim3(1, 32, 8), 256>>>(out_adj, H0B, PART, NT_, EMB_, NT_);
    reduce_split_k<<<512, 256>>>(PART, 8, (size_t)NT_ * EMB_, EMB_, gcn_b1, 1, X1B);
    gemm_n3_k<<<(NT_ * 32 + 255) / 256, 256>>>(X1B, gcn_W2, nullptr, H2B, NT_, EMB_);
    gemm_n3_k<<<(NT_ * 32 + 255) / 256, 256>>>(out_adj, H2B, gcn_b2, X2B, NT_, NT_);
    logsoftmax_k<<<(NT_ + 255) / 256, 256>>>(X2B, logits, NT_);
}